// round 11
// baseline (speedup 1.0000x reference)
#include <cuda_runtime.h>

#define KSEL     5000
#define CAP      65536
#define SMEMCAP  12288
#define THREADS  512
#define GRID     296
#define NPT_CAND 24          // SMEMCAP / THREADS
#define BUFCAP   2048
#define XGUESS   3.55f
#define NHIST    4096
#define NB       8192
#define EQ_N     1024
#define DST_N    5120
#define FIN_SMEM (DST_N*8 + NB*4 + EQ_N*4)   // 77824 bytes

// ---------------- scratch (static device globals; zero-initialized) ---------
__device__ unsigned g_du[CAP];     // dense candidate keys (monotone u32)
__device__ unsigned g_didx[CAP];   // dense candidate original indices
__device__ unsigned g_hist[NHIST]; // coarse histogram of (key-UB)>>13
__device__ unsigned g_total;
__device__ unsigned g_ovf;
__device__ unsigned g_done;        // block completion counter

__device__ __forceinline__ unsigned f2u(float f) {
    unsigned b = __float_as_uint(f);
    return (b & 0x80000000u) ? ~b : (b | 0x80000000u);
}
__device__ __forceinline__ float u2f(unsigned u) {
    return __uint_as_float((u & 0x80000000u) ? (u & 0x7fffffffu) : ~u);
}

// ---- vectorized hierarchical inclusive SUFFIX scan (512 threads) -----------
template <int NBINS>
__device__ __forceinline__ void suffix_scan_block(unsigned* b, unsigned* wsum) {
    constexpr int NPT = NBINS / THREADS;
    constexpr int NV = NPT / 4;
    const unsigned tid = threadIdx.x;
    const unsigned lane = tid & 31u, wid = tid >> 5;
    uint4* b4 = (uint4*)b;
    unsigned v[NPT]; unsigned tsum = 0;
    #pragma unroll
    for (int q = 0; q < NV; q++) {
        uint4 t4 = b4[tid * NV + q];
        v[q*4+0]=t4.x; v[q*4+1]=t4.y; v[q*4+2]=t4.z; v[q*4+3]=t4.w;
    }
    #pragma unroll
    for (int k = 0; k < NPT; k++) tsum += v[k];
    unsigned inc = tsum;
    #pragma unroll
    for (int d = 1; d < 32; d <<= 1) {
        unsigned o = __shfl_down_sync(0xffffffffu, inc, d);
        if (lane + d < 32) inc += o;
    }
    if (lane == 0) wsum[wid] = inc;
    __syncthreads();
    if (wid == 0) {
        unsigned w = (lane < 16u) ? wsum[lane] : 0u;
        unsigned wi = w;
        #pragma unroll
        for (int d = 1; d < 32; d <<= 1) {
            unsigned o = __shfl_down_sync(0xffffffffu, wi, d);
            if (lane + d < 32) wi += o;
        }
        if (lane < 16u) wsum[lane] = wi - w;   // sum of warps after this warp
    }
    __syncthreads();
    unsigned acc = wsum[wid] + (inc - tsum);
    #pragma unroll
    for (int k = NPT - 1; k >= 0; k--) { acc += v[k]; v[k] = acc; }
    #pragma unroll
    for (int q = 0; q < NV; q++)
        b4[tid * NV + q] = make_uint4(v[q*4+0], v[q*4+1], v[q*4+2], v[q*4+3]);
    __syncthreads();
}

// ---- vectorized hierarchical EXCLUSIVE scan over NB bins (512 threads) -----
__device__ __forceinline__ void excl_scan_nb(unsigned* b, unsigned* wsum) {
    constexpr int NPT = NB / THREADS;   // 16
    constexpr int NV = NPT / 4;         // 4
    const unsigned tid = threadIdx.x;
    const unsigned lane = tid & 31u, wid = tid >> 5;
    uint4* b4 = (uint4*)b;
    unsigned v[NPT], pre[NPT]; unsigned tsum = 0;
    #pragma unroll
    for (int q = 0; q < NV; q++) {
        uint4 t4 = b4[tid * NV + q];
        v[q*4+0]=t4.x; v[q*4+1]=t4.y; v[q*4+2]=t4.z; v[q*4+3]=t4.w;
    }
    #pragma unroll
    for (int k = 0; k < NPT; k++) { pre[k] = tsum; tsum += v[k]; }
    unsigned inc = tsum;
    #pragma unroll
    for (int d = 1; d < 32; d <<= 1) {
        unsigned o = __shfl_up_sync(0xffffffffu, inc, d);
        if (lane >= (unsigned)d) inc += o;
    }
    if (lane == 31) wsum[wid] = inc;
    __syncthreads();
    if (wid == 0) {
        unsigned w = (lane < 16u) ? wsum[lane] : 0u;
        unsigned wi = w;
        #pragma unroll
        for (int d = 1; d < 32; d <<= 1) {
            unsigned o = __shfl_up_sync(0xffffffffu, wi, d);
            if (lane >= (unsigned)d) wi += o;
        }
        if (lane < 16u) wsum[lane] = wi - w;
    }
    __syncthreads();
    unsigned base = wsum[wid] + (inc - tsum);
    #pragma unroll
    for (int q = 0; q < NV; q++)
        b4[tid * NV + q] = make_uint4(base+pre[q*4+0], base+pre[q*4+1],
                                      base+pre[q*4+2], base+pre[q*4+3]);
    __syncthreads();
}

// ---------------- THE kernel: stream + last-block select/sort/output --------
__global__ void __launch_bounds__(THREADS, 2)
k_all(const float* __restrict__ x, int n, float* __restrict__ out) {
    extern __shared__ unsigned long long sm[];
    unsigned long long* dst = sm;                   // DST_N u64 (final phase)
    unsigned* bcnt = (unsigned*)(dst + DST_N);      // NB u32
    unsigned* eq   = bcnt + NB;                     // EQ_N u32
    unsigned* skey = (unsigned*)sm;                 // BUFCAP u32 (stream overlay)
    unsigned* sidx = skey + BUFCAP;                 // BUFCAP u32
    __shared__ unsigned s_cnt, s_base, sh_d, sh_ab, s_neq, s_last, wsum[16];
    const unsigned tid = threadIdx.x;
    const unsigned UB = f2u(XGUESS);

    // ================= phase 1: streaming compaction =========================
    if (tid == 0) s_cnt = 0;
    __syncthreads();
    {
        const int n4 = n >> 2;
        const float4* __restrict__ x4 = (const float4*)x;
        const int stride = gridDim.x * blockDim.x;
        int i = blockIdx.x * blockDim.x + tid;

        #define PROC4(v, base_) do {                                              \
            float mx = fmaxf(fmaxf((v).x, (v).y), fmaxf((v).z, (v).w));           \
            unsigned am = __activemask();                                         \
            if (__ballot_sync(am, mx > XGUESS)) {                                 \
                if ((v).x > XGUESS) { unsigned p = atomicAdd(&s_cnt, 1u); if (p < BUFCAP) { skey[p] = f2u((v).x); sidx[p] = (base_) + 0; } } \
                if ((v).y > XGUESS) { unsigned p = atomicAdd(&s_cnt, 1u); if (p < BUFCAP) { skey[p] = f2u((v).y); sidx[p] = (base_) + 1; } } \
                if ((v).z > XGUESS) { unsigned p = atomicAdd(&s_cnt, 1u); if (p < BUFCAP) { skey[p] = f2u((v).z); sidx[p] = (base_) + 2; } } \
                if ((v).w > XGUESS) { unsigned p = atomicAdd(&s_cnt, 1u); if (p < BUFCAP) { skey[p] = f2u((v).w); sidx[p] = (base_) + 3; } } \
            }                                                                     \
        } while (0)

        for (; i + 3 * stride < n4; i += 4 * stride) {
            float4 a = __ldcs(x4 + i);
            float4 b = __ldcs(x4 + i + stride);
            float4 c = __ldcs(x4 + i + 2 * stride);
            float4 d = __ldcs(x4 + i + 3 * stride);
            PROC4(a, (unsigned)i << 2);
            PROC4(b, (unsigned)(i + stride) << 2);
            PROC4(c, (unsigned)(i + 2 * stride) << 2);
            PROC4(d, (unsigned)(i + 3 * stride) << 2);
        }
        for (; i < n4; i += stride) {
            float4 a = __ldcs(x4 + i);
            PROC4(a, (unsigned)i << 2);
        }
        if (blockIdx.x == 0) {   // scalar tail
            for (int t = (n4 << 2) + tid; t < n; t += blockDim.x) {
                float v = x[t];
                if (v > XGUESS) { unsigned p = atomicAdd(&s_cnt, 1u); if (p < BUFCAP) { skey[p] = f2u(v); sidx[p] = (unsigned)t; } }
            }
        }
    }
    __syncthreads();
    {
        unsigned cnt = s_cnt;
        if (cnt > BUFCAP) { if (tid == 0) g_ovf = 1u; cnt = BUFCAP; }
        if (tid == 0) s_base = atomicAdd(&g_total, cnt);
        __syncthreads();
        unsigned base = s_base;
        for (unsigned j = tid; j < cnt; j += blockDim.x) {
            unsigned q = base + j;
            unsigned key = skey[j];
            if (q < CAP) { g_du[q] = key; g_didx[q] = sidx[j]; }
            unsigned b = (key - UB) >> 13; if (b > NHIST - 1u) b = NHIST - 1u;
            atomicAdd(&g_hist[b], 1u);
        }
    }

    // ================= device-wide completion: last block continues ==========
    __threadfence();
    __syncthreads();
    if (tid == 0) s_last = (atomicAdd(&g_done, 1u) == (unsigned)(gridDim.x - 1)) ? 1u : 0u;
    __syncthreads();
    if (!s_last) return;
    __threadfence();

    // ================= phase 2 (last block only): select + sort + output =====
    unsigned tot = g_total;
    bool need_fb = !((g_ovf == 0u) && tot >= (unsigned)KSEL && tot <= (unsigned)SMEMCAP
                     && (g_hist[NHIST - 1] < (unsigned)KSEL));
    unsigned T = tot > (unsigned)SMEMCAP ? (unsigned)SMEMCAP : tot;

    // register-resident candidate keys (key 0 == invalid slot)
    unsigned uk[NPT_CAND];
    #pragma unroll
    for (int k = 0; k < NPT_CAND; k++) {
        unsigned j = tid + (unsigned)k * THREADS;
        uk[k] = (j < T) ? g_du[j] : 0u;
    }

    unsigned uT = 0, R0 = 0, neq = 0;
    if (!need_fb) {
        // coarse suffix scan over g_hist
        for (unsigned t = tid; t < NHIST; t += THREADS) bcnt[t] = g_hist[t];
        __syncthreads();
        suffix_scan_block<NHIST>(bcnt, wsum);
        for (unsigned t = tid; t < NHIST; t += THREADS) {
            unsigned nxt = (t + 1 < NHIST) ? bcnt[t + 1] : 0;
            if (bcnt[t] >= (unsigned)KSEL && nxt < (unsigned)KSEL) { sh_d = t; sh_ab = nxt; }
        }
        __syncthreads();
        const unsigned d = sh_d;
        const unsigned need2 = (unsigned)KSEL - sh_ab;
        __syncthreads();

        // fine histogram (1-key-wide bins) from registers
        for (unsigned t = tid; t < NB; t += THREADS) bcnt[t] = 0;
        __syncthreads();
        #pragma unroll
        for (int k = 0; k < NPT_CAND; k++) {
            unsigned del = uk[k] - UB;
            if ((del >> 13) == d) atomicAdd(&bcnt[del & (NB - 1u)], 1u);
        }
        __syncthreads();
        suffix_scan_block<NB>(bcnt, wsum);
        for (unsigned t = tid; t < NB; t += THREADS) {
            unsigned nxt = (t + 1 < NB) ? bcnt[t + 1] : 0;
            if (bcnt[t] >= need2 && nxt < need2) { sh_d = t; sh_ab = nxt; }
        }
        __syncthreads();
        uT = UB + (d << 13) + sh_d;       // exact threshold key
        R0 = need2 - sh_ab;               // ties to keep
        __syncthreads();
    }

    // tie-collect (tiny; warp-aggregated)
    if (!need_fb && R0 > 0) {
        if (tid == 0) s_neq = 0;
        __syncthreads();
        #pragma unroll
        for (int k = 0; k < NPT_CAND; k++) {
            bool pred = (uk[k] == uT);
            unsigned ix = pred ? g_didx[tid + (unsigned)k * THREADS] : 0u;
            unsigned mask = __ballot_sync(0xffffffffu, pred);
            if (mask) {
                unsigned lane = tid & 31u;
                unsigned leader = (unsigned)(__ffs(mask) - 1);
                unsigned wbase = 0;
                if (lane == leader) wbase = atomicAdd(&s_neq, (unsigned)__popc(mask));
                wbase = __shfl_sync(0xffffffffu, wbase, leader);
                if (pred) {
                    unsigned pos = wbase + (unsigned)__popc(mask & ((1u << lane) - 1u));
                    if (pos < EQ_N) eq[pos] = ix;
                }
            }
        }
        __syncthreads();
        neq = s_neq;
        if (neq > EQ_N) need_fb = true;   // absurd tie count -> exact slow path
    }

    if (need_fb) {
        // ===== exact full-input fallback (never runs on sane inputs) =========
        unsigned* bins = bcnt;
        unsigned prefix = 0, prefmask = 0, need = KSEL;
        const int vsh[3] = { 21, 10, 0 };
        const int vwd[3] = { 11, 11, 10 };
        for (int r = 0; r < 3; r++) {
            const int sh = vsh[r];
            const int nb = 1 << vwd[r];
            for (int t = tid; t < nb; t += THREADS) bins[t] = 0;
            __syncthreads();
            for (int i = tid; i < n; i += THREADS) {
                unsigned u = f2u(x[i]);
                if ((u & prefmask) == prefix) {
                    unsigned b = (u >> sh) & (unsigned)(nb - 1);
                    unsigned am = __activemask();
                    unsigned peers = __match_any_sync(am, b);
                    if ((tid & 31u) == (unsigned)(__ffs(peers) - 1))
                        atomicAdd(&bins[b], (unsigned)__popc(peers));
                }
            }
            __syncthreads();
            for (int d2 = 1; d2 < nb; d2 <<= 1) {      // suffix Hillis-Steele
                unsigned tmp[4]; int c = 0;
                for (int t = tid; t < nb; t += THREADS)
                    tmp[c++] = (t + d2 < nb) ? bins[t + d2] : 0;
                __syncthreads();
                c = 0;
                for (int t = tid; t < nb; t += THREADS) bins[t] += tmp[c++];
                __syncthreads();
            }
            for (int t = tid; t < nb; t += THREADS) {
                unsigned nxt = (t + 1 < nb) ? bins[t + 1] : 0;
                if (bins[t] >= need && nxt < need) sh_d = (unsigned)t;
            }
            __syncthreads();
            unsigned d2 = sh_d;
            unsigned above = (d2 + 1 < (unsigned)nb) ? bins[d2 + 1] : 0;
            __syncthreads();
            need -= above;
            prefix |= d2 << sh;
            prefmask |= ((unsigned)(nb - 1)) << sh;
        }
        const unsigned uTf = prefix;
        const unsigned Rf = need;

        unsigned iprefix = 0, imask = 0, needi = Rf;
        const int ish[3] = { 15, 4, 0 };
        const int iwd[3] = { 11, 11, 4 };
        if (Rf > 0) {
            for (int r = 0; r < 3; r++) {
                const int sh = ish[r];
                const int nb = 1 << iwd[r];
                for (int t = tid; t < nb; t += THREADS) bins[t] = 0;
                __syncthreads();
                for (int i = tid; i < n; i += THREADS) {
                    unsigned u = f2u(x[i]);
                    if (u == uTf && (((unsigned)i & imask) == iprefix))
                        atomicAdd(&bins[((unsigned)i >> sh) & (unsigned)(nb - 1)], 1u);
                }
                __syncthreads();
                for (int d2 = 1; d2 < nb; d2 <<= 1) {  // prefix Hillis-Steele
                    unsigned tmp[4]; int c = 0;
                    for (int t = tid; t < nb; t += THREADS)
                        tmp[c++] = (t >= d2) ? bins[t - d2] : 0;
                    __syncthreads();
                    c = 0;
                    for (int t = tid; t < nb; t += THREADS) bins[t] += tmp[c++];
                    __syncthreads();
                }
                for (int t = tid; t < nb; t += THREADS) {
                    unsigned prev = (t > 0) ? bins[t - 1] : 0;
                    if (bins[t] >= needi && prev < needi) sh_d = (unsigned)t;
                }
                __syncthreads();
                unsigned d2 = sh_d;
                unsigned below = (d2 > 0) ? bins[d2 - 1] : 0;
                __syncthreads();
                needi -= below;
                iprefix |= d2 << sh;
                imask |= ((unsigned)(nb - 1)) << sh;
            }
        }
        if (tid == 0) g_total = 0;
        __syncthreads();
        for (int i = tid; i < n; i += THREADS) {
            unsigned u = f2u(x[i]);
            bool keep = (u > uTf) || (Rf > 0 && u == uTf && (unsigned)i <= iprefix);
            if (keep) {
                unsigned p = atomicAdd(&g_total, 1u);
                if (p < CAP) { g_du[p] = u; g_didx[p] = (unsigned)i; }
            }
        }
        __syncthreads();
        T = g_total; if (T > (unsigned)SMEMCAP) T = SMEMCAP;   // == KSEL
        #pragma unroll
        for (int k = 0; k < NPT_CAND; k++) {
            unsigned j = tid + (unsigned)k * THREADS;
            uk[k] = (j < T) ? g_du[j] : 0u;
        }
        uT = 0; R0 = 0; neq = 0;          // every staged candidate is a winner
        __syncthreads();
    }

    unsigned R = R0; if (R > neq) R = neq;
    unsigned cut = 0xffffffffu;           // keep all ties when neq == R
    if (R > 0 && neq > R) {
        unsigned np2 = 2; while (np2 < neq) np2 <<= 1;
        for (unsigned t = tid; t < np2; t += THREADS)
            if (t >= neq) eq[t] = 0xffffffffu;
        __syncthreads();
        for (unsigned k = 2; k <= np2; k <<= 1) {
            for (unsigned j = k >> 1; j > 0; j >>= 1) {
                for (unsigned t = tid; t < np2 / 2; t += THREADS) {
                    unsigned i2 = ((t & ~(j - 1)) << 1) | (t & (j - 1));
                    unsigned p2 = i2 | j;
                    unsigned a = eq[i2], b = eq[p2];
                    bool up = ((i2 & k) == 0);
                    if ((a > b) == up) { eq[i2] = b; eq[p2] = a; }
                }
                __syncthreads();
            }
        }
        cut = eq[R - 1];
        __syncthreads();
    }

    // ---- bucket sort by original index: bucket = idx >> 13
    for (unsigned t = tid; t < NB; t += THREADS) bcnt[t] = 0;
    __syncthreads();
    #pragma unroll
    for (int k = 0; k < NPT_CAND; k++) {
        unsigned u = uk[k];
        bool gt = (u > uT);
        bool tie = (R > 0 && u == uT);
        unsigned ix = (gt || tie) ? g_didx[tid + (unsigned)k * THREADS] : 0u;
        bool keep = gt || (tie && ix <= cut);
        if (keep) atomicAdd(&bcnt[ix >> 13], 1u);
    }
    __syncthreads();

    excl_scan_nb(bcnt, wsum);

    #pragma unroll
    for (int k = 0; k < NPT_CAND; k++) {
        unsigned u = uk[k];
        bool gt = (u > uT);
        bool tie = (R > 0 && u == uT);
        unsigned ix = (gt || tie) ? g_didx[tid + (unsigned)k * THREADS] : 0u;
        bool keep = gt || (tie && ix <= cut);
        if (keep) {
            unsigned r = atomicAdd(&bcnt[ix >> 13], 1u);
            if (r < (unsigned)DST_N)
                dst[r] = ((unsigned long long)ix << 32) | (unsigned long long)u;
        }
    }
    __syncthreads();

    // tiny per-bucket insertion sorts
    for (unsigned b = tid; b < NB; b += THREADS) {
        unsigned s0 = (b > 0) ? bcnt[b - 1] : 0;
        unsigned e0 = bcnt[b];
        if (s0 > (unsigned)DST_N) s0 = DST_N;
        if (e0 > (unsigned)DST_N) e0 = DST_N;
        for (unsigned i2 = s0 + 1; i2 < e0; i2++) {
            unsigned long long key = dst[i2];
            unsigned j2 = i2;
            while (j2 > s0 && dst[j2 - 1] > key) { dst[j2] = dst[j2 - 1]; j2--; }
            dst[j2] = key;
        }
    }
    __syncthreads();

    for (unsigned t = tid; t < KSEL; t += THREADS)
        out[t] = u2f((unsigned)(dst[t] & 0xffffffffu));

    // restore invariants for next graph replay
    for (unsigned t = tid; t < NHIST; t += THREADS) g_hist[t] = 0;
    if (tid == 0) { g_total = 0; g_ovf = 0; g_done = 0; }
}

// ---------------- launch ----------------------------------------------------
extern "C" void kernel_launch(void* const* d_in, const int* in_sizes, int n_in,
                              void* d_out, int out_size) {
    const float* x = (const float*)d_in[0];
    int n = in_sizes[0];
    float* out = (float*)d_out;

    cudaFuncSetAttribute(k_all, cudaFuncAttributeMaxDynamicSharedMemorySize, FIN_SMEM);
    k_all<<<GRID, THREADS, FIN_SMEM>>>(x, n, out);
}

// round 12
// speedup vs baseline: 1.0326x; 1.0326x over previous
#include <cuda_runtime.h>

#define KSEL     5000
#define CAP      65536
#define SMEMCAP  12288
#define THREADS  512
#define NPT_CAND 24          // SMEMCAP / THREADS
#define BUFCAP   2048
#define XGUESS   3.55f
#define NHIST    4096
#define NB       8192
#define EQB      1024
#define DST_N    5120
#define FIN_SMEM (DST_N*8 + NB*4 + EQB*8)   // 81920 bytes

// ---------------- scratch (static device globals; zero-initialized) ---------
__device__ unsigned g_du[CAP];     // dense candidate keys (monotone u32)
__device__ unsigned g_didx[CAP];   // dense candidate original indices
__device__ unsigned g_hist[NHIST]; // coarse histogram of (key-UB)>>13
__device__ unsigned g_total;
__device__ unsigned g_ovf;

__device__ __forceinline__ unsigned f2u(float f) {
    unsigned b = __float_as_uint(f);
    return (b & 0x80000000u) ? ~b : (b | 0x80000000u);
}
__device__ __forceinline__ float u2f(unsigned u) {
    return __uint_as_float((u & 0x80000000u) ? (u & 0x7fffffffu) : ~u);
}

// ---------------- K1: streaming compaction + coarse histogram (proven) ------
__global__ void __launch_bounds__(512) k_compact(const float* __restrict__ x, int n) {
    __shared__ unsigned s_cnt, s_base;
    __shared__ unsigned skey[BUFCAP];
    __shared__ unsigned sidx[BUFCAP];
    if (threadIdx.x == 0) s_cnt = 0;
    __syncthreads();

    const int n4 = n >> 2;
    const float4* __restrict__ x4 = (const float4*)x;
    const int stride = gridDim.x * blockDim.x;
    int i = blockIdx.x * blockDim.x + threadIdx.x;

    #define PROC4(v, base_) do {                                                  \
        float mx = fmaxf(fmaxf((v).x, (v).y), fmaxf((v).z, (v).w));               \
        unsigned am = __activemask();                                             \
        if (__ballot_sync(am, mx > XGUESS)) {                                     \
            if ((v).x > XGUESS) { unsigned p = atomicAdd(&s_cnt, 1u); if (p < BUFCAP) { skey[p] = f2u((v).x); sidx[p] = (base_) + 0; } } \
            if ((v).y > XGUESS) { unsigned p = atomicAdd(&s_cnt, 1u); if (p < BUFCAP) { skey[p] = f2u((v).y); sidx[p] = (base_) + 1; } } \
            if ((v).z > XGUESS) { unsigned p = atomicAdd(&s_cnt, 1u); if (p < BUFCAP) { skey[p] = f2u((v).z); sidx[p] = (base_) + 2; } } \
            if ((v).w > XGUESS) { unsigned p = atomicAdd(&s_cnt, 1u); if (p < BUFCAP) { skey[p] = f2u((v).w); sidx[p] = (base_) + 3; } } \
        }                                                                         \
    } while (0)

    for (; i + 3 * stride < n4; i += 4 * stride) {
        float4 a = __ldcs(x4 + i);
        float4 b = __ldcs(x4 + i + stride);
        float4 c = __ldcs(x4 + i + 2 * stride);
        float4 d = __ldcs(x4 + i + 3 * stride);
        PROC4(a, (unsigned)i << 2);
        PROC4(b, (unsigned)(i + stride) << 2);
        PROC4(c, (unsigned)(i + 2 * stride) << 2);
        PROC4(d, (unsigned)(i + 3 * stride) << 2);
    }
    for (; i < n4; i += stride) {
        float4 a = __ldcs(x4 + i);
        PROC4(a, (unsigned)i << 2);
    }
    if (blockIdx.x == 0) {       // scalar tail (n not divisible by 4)
        for (int t = (n4 << 2) + threadIdx.x; t < n; t += blockDim.x) {
            float v = x[t];
            if (v > XGUESS) { unsigned p = atomicAdd(&s_cnt, 1u); if (p < BUFCAP) { skey[p] = f2u(v); sidx[p] = (unsigned)t; } }
        }
    }
    __syncthreads();

    unsigned cnt = s_cnt;
    if (cnt > BUFCAP) { if (threadIdx.x == 0) g_ovf = 1u; cnt = BUFCAP; }
    if (threadIdx.x == 0) s_base = atomicAdd(&g_total, cnt);
    __syncthreads();
    const unsigned UB = f2u(XGUESS);
    unsigned base = s_base;
    for (unsigned j = threadIdx.x; j < cnt; j += blockDim.x) {
        unsigned q = base + j;
        unsigned key = skey[j];
        if (q < CAP) { g_du[q] = key; g_didx[q] = sidx[j]; }
        unsigned b = (key - UB) >> 13; if (b > NHIST - 1u) b = NHIST - 1u;
        atomicAdd(&g_hist[b], 1u);
    }
}

// ---- vectorized hierarchical inclusive SUFFIX scan (512 threads) -----------
template <int NBINS>
__device__ __forceinline__ void suffix_scan_block(unsigned* b, unsigned* wsum) {
    constexpr int NPT = NBINS / THREADS;
    constexpr int NV = NPT / 4;
    const unsigned tid = threadIdx.x;
    const unsigned lane = tid & 31u, wid = tid >> 5;
    uint4* b4 = (uint4*)b;
    unsigned v[NPT]; unsigned tsum = 0;
    #pragma unroll
    for (int q = 0; q < NV; q++) {
        uint4 t4 = b4[tid * NV + q];
        v[q*4+0]=t4.x; v[q*4+1]=t4.y; v[q*4+2]=t4.z; v[q*4+3]=t4.w;
    }
    #pragma unroll
    for (int k = 0; k < NPT; k++) tsum += v[k];
    unsigned inc = tsum;
    #pragma unroll
    for (int d = 1; d < 32; d <<= 1) {
        unsigned o = __shfl_down_sync(0xffffffffu, inc, d);
        if (lane + d < 32) inc += o;
    }
    if (lane == 0) wsum[wid] = inc;
    __syncthreads();
    if (wid == 0) {
        unsigned w = (lane < 16u) ? wsum[lane] : 0u;
        unsigned wi = w;
        #pragma unroll
        for (int d = 1; d < 32; d <<= 1) {
            unsigned o = __shfl_down_sync(0xffffffffu, wi, d);
            if (lane + d < 32) wi += o;
        }
        if (lane < 16u) wsum[lane] = wi - w;   // sum of warps after this warp
    }
    __syncthreads();
    unsigned acc = wsum[wid] + (inc - tsum);
    #pragma unroll
    for (int k = NPT - 1; k >= 0; k--) { acc += v[k]; v[k] = acc; }
    #pragma unroll
    for (int q = 0; q < NV; q++)
        b4[tid * NV + q] = make_uint4(v[q*4+0], v[q*4+1], v[q*4+2], v[q*4+3]);
    __syncthreads();
}

// ---- vectorized hierarchical EXCLUSIVE scan over NB bins (512 threads) -----
__device__ __forceinline__ void excl_scan_nb(unsigned* b, unsigned* wsum) {
    constexpr int NPT = NB / THREADS;   // 16
    constexpr int NV = NPT / 4;         // 4
    const unsigned tid = threadIdx.x;
    const unsigned lane = tid & 31u, wid = tid >> 5;
    uint4* b4 = (uint4*)b;
    unsigned v[NPT], pre[NPT]; unsigned tsum = 0;
    #pragma unroll
    for (int q = 0; q < NV; q++) {
        uint4 t4 = b4[tid * NV + q];
        v[q*4+0]=t4.x; v[q*4+1]=t4.y; v[q*4+2]=t4.z; v[q*4+3]=t4.w;
    }
    #pragma unroll
    for (int k = 0; k < NPT; k++) { pre[k] = tsum; tsum += v[k]; }
    unsigned inc = tsum;
    #pragma unroll
    for (int d = 1; d < 32; d <<= 1) {
        unsigned o = __shfl_up_sync(0xffffffffu, inc, d);
        if (lane >= (unsigned)d) inc += o;
    }
    if (lane == 31) wsum[wid] = inc;
    __syncthreads();
    if (wid == 0) {
        unsigned w = (lane < 16u) ? wsum[lane] : 0u;
        unsigned wi = w;
        #pragma unroll
        for (int d = 1; d < 32; d <<= 1) {
            unsigned o = __shfl_up_sync(0xffffffffu, wi, d);
            if (lane >= (unsigned)d) wi += o;
        }
        if (lane < 16u) wsum[lane] = wi - w;
    }
    __syncthreads();
    unsigned base = wsum[wid] + (inc - tsum);
    #pragma unroll
    for (int q = 0; q < NV; q++)
        b4[tid * NV + q] = make_uint4(base+pre[q*4+0], base+pre[q*4+1],
                                      base+pre[q*4+2], base+pre[q*4+3]);
    __syncthreads();
}

// ---- exact full-input fallback (cold, never runs on sane inputs) -----------
__device__ __noinline__ void run_fallback(const float* __restrict__ x, int n,
                                          unsigned* bins, unsigned* psh) {
    const unsigned tid = threadIdx.x;
    unsigned prefix = 0, prefmask = 0, need = KSEL;
    const int vsh[3] = { 21, 10, 0 };
    const int vwd[3] = { 11, 11, 10 };
    for (int r = 0; r < 3; r++) {
        const int sh = vsh[r];
        const int nb = 1 << vwd[r];
        for (int t = tid; t < nb; t += THREADS) bins[t] = 0;
        __syncthreads();
        for (int i = tid; i < n; i += THREADS) {
            unsigned u = f2u(x[i]);
            if ((u & prefmask) == prefix) {
                unsigned b = (u >> sh) & (unsigned)(nb - 1);
                unsigned am = __activemask();
                unsigned peers = __match_any_sync(am, b);
                if ((tid & 31u) == (unsigned)(__ffs(peers) - 1))
                    atomicAdd(&bins[b], (unsigned)__popc(peers));
            }
        }
        __syncthreads();
        for (int d2 = 1; d2 < nb; d2 <<= 1) {      // suffix Hillis-Steele
            unsigned tmp[4]; int c = 0;
            for (int t = tid; t < nb; t += THREADS)
                tmp[c++] = (t + d2 < nb) ? bins[t + d2] : 0;
            __syncthreads();
            c = 0;
            for (int t = tid; t < nb; t += THREADS) bins[t] += tmp[c++];
            __syncthreads();
        }
        for (int t = tid; t < nb; t += THREADS) {
            unsigned nxt = (t + 1 < nb) ? bins[t + 1] : 0;
            if (bins[t] >= need && nxt < need) *psh = (unsigned)t;
        }
        __syncthreads();
        unsigned d2 = *psh;
        unsigned above = (d2 + 1 < (unsigned)nb) ? bins[d2 + 1] : 0;
        __syncthreads();
        need -= above;
        prefix |= d2 << sh;
        prefmask |= ((unsigned)(nb - 1)) << sh;
    }
    const unsigned uTf = prefix;
    const unsigned Rf = need;

    unsigned iprefix = 0, imask = 0, needi = Rf;
    const int ish[3] = { 15, 4, 0 };
    const int iwd[3] = { 11, 11, 4 };
    if (Rf > 0) {
        for (int r = 0; r < 3; r++) {
            const int sh = ish[r];
            const int nb = 1 << iwd[r];
            for (int t = tid; t < nb; t += THREADS) bins[t] = 0;
            __syncthreads();
            for (int i = tid; i < n; i += THREADS) {
                unsigned u = f2u(x[i]);
                if (u == uTf && (((unsigned)i & imask) == iprefix))
                    atomicAdd(&bins[((unsigned)i >> sh) & (unsigned)(nb - 1)], 1u);
            }
            __syncthreads();
            for (int d2 = 1; d2 < nb; d2 <<= 1) {  // prefix Hillis-Steele
                unsigned tmp[4]; int c = 0;
                for (int t = tid; t < nb; t += THREADS)
                    tmp[c++] = (t >= d2) ? bins[t - d2] : 0;
                __syncthreads();
                c = 0;
                for (int t = tid; t < nb; t += THREADS) bins[t] += tmp[c++];
                __syncthreads();
            }
            for (int t = tid; t < nb; t += THREADS) {
                unsigned prev = (t > 0) ? bins[t - 1] : 0;
                if (bins[t] >= needi && prev < needi) *psh = (unsigned)t;
            }
            __syncthreads();
            unsigned d2 = *psh;
            unsigned below = (d2 > 0) ? bins[d2 - 1] : 0;
            __syncthreads();
            needi -= below;
            iprefix |= d2 << sh;
            imask |= ((unsigned)(nb - 1)) << sh;
        }
    }
    if (tid == 0) g_total = 0;
    __syncthreads();
    for (int i = tid; i < n; i += THREADS) {
        unsigned u = f2u(x[i]);
        bool keep = (u > uTf) || (Rf > 0 && u == uTf && (unsigned)i <= iprefix);
        if (keep) {
            unsigned p = atomicAdd(&g_total, 1u);
            if (p < CAP) { g_du[p] = u; g_didx[p] = (unsigned)i; }
        }
    }
    __syncthreads();
}

// ---------------- K2: select via bin-d gather + bucket sort + output --------
__global__ void __launch_bounds__(THREADS) k_final(const float* __restrict__ x, int n,
                                                   float* __restrict__ out) {
    extern __shared__ unsigned long long sm[];
    unsigned long long* dst = sm;                   // DST_N u64 (idx<<32|key)
    unsigned* bcnt = (unsigned*)(dst + DST_N);      // NB u32
    unsigned long long* eqb = (unsigned long long*)(bcnt + NB);  // EQB u64
    __shared__ unsigned sh_d, sh_ab, s_cnt, wsum[16];
    const unsigned tid = threadIdx.x;
    const unsigned UB = f2u(XGUESS);

    unsigned tot = g_total;
    bool need_fb = !((g_ovf == 0u) && tot >= (unsigned)KSEL && tot <= (unsigned)SMEMCAP
                     && (g_hist[NHIST - 1] < (unsigned)KSEL));
    unsigned T = tot > (unsigned)SMEMCAP ? (unsigned)SMEMCAP : tot;

    // register-resident candidate keys (key 0 == invalid slot)
    unsigned uk[NPT_CAND];
    #pragma unroll
    for (int k = 0; k < NPT_CAND; k++) {
        unsigned j = tid + (unsigned)k * THREADS;
        uk[k] = (j < T) ? g_du[j] : 0u;
    }

    unsigned uT = 0, cut = 0xffffffffu;
    if (!need_fb) {
        // coarse suffix scan over g_hist (4096 bins)
        for (unsigned t = tid; t < NHIST; t += THREADS) bcnt[t] = g_hist[t];
        __syncthreads();
        suffix_scan_block<NHIST>(bcnt, wsum);
        for (unsigned t = tid; t < NHIST; t += THREADS) {
            unsigned nxt = (t + 1 < NHIST) ? bcnt[t + 1] : 0;
            if (bcnt[t] >= (unsigned)KSEL && nxt < (unsigned)KSEL) { sh_d = t; sh_ab = nxt; }
        }
        __syncthreads();
        const unsigned d = sh_d;
        const unsigned need2 = (unsigned)KSEL - sh_ab;   // >= 1
        const unsigned cnt_d = bcnt[d] - sh_ab;          // candidates in bin d
        __syncthreads();

        if (cnt_d > (unsigned)EQB) {
            need_fb = true;
        } else {
            // gather bin-d entries: e = (key<<32) | ~idx  (warp-aggregated)
            if (tid == 0) s_cnt = 0;
            __syncthreads();
            #pragma unroll
            for (int k = 0; k < NPT_CAND; k++) {
                unsigned j = tid + (unsigned)k * THREADS;
                bool pred = (j < T) && (((uk[k] - UB) >> 13) == d);
                unsigned mask = __ballot_sync(0xffffffffu, pred);
                if (mask) {
                    unsigned lane = tid & 31u;
                    unsigned leader = (unsigned)(__ffs(mask) - 1);
                    unsigned wbase = 0;
                    if (lane == leader) wbase = atomicAdd(&s_cnt, (unsigned)__popc(mask));
                    wbase = __shfl_sync(0xffffffffu, wbase, leader);
                    if (pred) {
                        unsigned pos = wbase + (unsigned)__popc(mask & ((1u << lane) - 1u));
                        if (pos < (unsigned)EQB)
                            eqb[pos] = ((unsigned long long)uk[k] << 32)
                                     | (unsigned long long)(~g_didx[j]);
                    }
                }
            }
            __syncthreads();
            unsigned m = s_cnt;                      // == cnt_d
            unsigned np2 = 2; while (np2 < m) np2 <<= 1;
            for (unsigned t = tid; t < np2; t += THREADS)
                if (t >= m) eqb[t] = 0ull;           // pad (sorts last, descending)
            __syncthreads();
            // bitonic sort DESCENDING over np2 entries
            for (unsigned k2 = 2; k2 <= np2; k2 <<= 1) {
                for (unsigned j2 = k2 >> 1; j2 > 0; j2 >>= 1) {
                    for (unsigned t = tid; t < np2 / 2; t += THREADS) {
                        unsigned i2 = ((t & ~(j2 - 1)) << 1) | (t & (j2 - 1));
                        unsigned p2 = i2 | j2;
                        unsigned long long a = eqb[i2], b = eqb[p2];
                        bool up = ((i2 & k2) == 0);
                        if ((a < b) == up) { eqb[i2] = b; eqb[p2] = a; }
                    }
                    __syncthreads();
                }
            }
            unsigned long long e = eqb[need2 - 1];   // exact boundary entry
            uT = (unsigned)(e >> 32);
            cut = ~(unsigned)e;                      // largest kept idx among key==uT
            __syncthreads();
        }
    }

    if (need_fb) {
        run_fallback(x, n, bcnt, &sh_d);
        T = g_total; if (T > (unsigned)SMEMCAP) T = SMEMCAP;   // == KSEL
        #pragma unroll
        for (int k = 0; k < NPT_CAND; k++) {
            unsigned j = tid + (unsigned)k * THREADS;
            uk[k] = (j < T) ? g_du[j] : 0u;
        }
        uT = 0; cut = 0xffffffffu;       // every staged candidate is a winner
        __syncthreads();
    }

    // ---- bucket sort by original index: bucket = idx >> 13
    for (unsigned t = tid; t < NB; t += THREADS) bcnt[t] = 0;
    __syncthreads();
    #pragma unroll
    for (int k = 0; k < NPT_CAND; k++) {
        unsigned j = tid + (unsigned)k * THREADS;
        bool vld = (j < T);
        unsigned u = uk[k];
        bool pre = vld && (u >= uT);
        unsigned ix = pre ? g_didx[j] : 0u;
        bool keep = vld && ((u > uT) || (u == uT && ix <= cut));
        if (keep) atomicAdd(&bcnt[ix >> 13], 1u);
    }
    __syncthreads();

    excl_scan_nb(bcnt, wsum);

    #pragma unroll
    for (int k = 0; k < NPT_CAND; k++) {
        unsigned j = tid + (unsigned)k * THREADS;
        bool vld = (j < T);
        unsigned u = uk[k];
        bool pre = vld && (u >= uT);
        unsigned ix = pre ? g_didx[j] : 0u;
        bool keep = vld && ((u > uT) || (u == uT && ix <= cut));
        if (keep) {
            unsigned r = atomicAdd(&bcnt[ix >> 13], 1u);
            if (r < (unsigned)DST_N)
                dst[r] = ((unsigned long long)ix << 32) | (unsigned long long)u;
        }
    }
    __syncthreads();

    // tiny per-bucket insertion sorts (bucket sizes ~0-6)
    for (unsigned b = tid; b < NB; b += THREADS) {
        unsigned s0 = (b > 0) ? bcnt[b - 1] : 0;
        unsigned e0 = bcnt[b];
        if (s0 > (unsigned)DST_N) s0 = DST_N;
        if (e0 > (unsigned)DST_N) e0 = DST_N;
        for (unsigned i2 = s0 + 1; i2 < e0; i2++) {
            unsigned long long key = dst[i2];
            unsigned j2 = i2;
            while (j2 > s0 && dst[j2 - 1] > key) { dst[j2] = dst[j2 - 1]; j2--; }
            dst[j2] = key;
        }
    }
    __syncthreads();

    for (unsigned t = tid; t < KSEL; t += THREADS)
        out[t] = u2f((unsigned)(dst[t] & 0xffffffffu));

    // restore invariants for next graph replay
    for (unsigned t = tid; t < NHIST; t += THREADS) g_hist[t] = 0;
    if (tid == 0) { g_total = 0; g_ovf = 0; }
}

// ---------------- launch ----------------------------------------------------
extern "C" void kernel_launch(void* const* d_in, const int* in_sizes, int n_in,
                              void* d_out, int out_size) {
    const float* x = (const float*)d_in[0];
    int n = in_sizes[0];
    float* out = (float*)d_out;

    cudaFuncSetAttribute(k_final, cudaFuncAttributeMaxDynamicSharedMemorySize, FIN_SMEM);

    k_compact<<<592, 512>>>(x, n);               // 148 SMs x 4 blocks: one wave
    k_final<<<1, THREADS, FIN_SMEM>>>(x, n, out);
}

// round 13
// speedup vs baseline: 1.1405x; 1.1045x over previous
#include <cuda_runtime.h>

#define KSEL     5000
#define CAP      65536
#define SMEMCAP  12288
#define FT       1024        // k_final / prep threads
#define NPT_CAND 12          // SMEMCAP / FT
#define BUFCAP   2048
#define XGUESS   3.55f
#define NHIST    4096
#define NB       8192
#define EQB      2048
#define DST_N    5120
#define FIN_SMEM (DST_N*8 + NB*4 + EQB*8)   // 90112 bytes

// ---------------- scratch (static device globals; zero-initialized) ---------
__device__ unsigned g_du[CAP];     // dense candidate keys (monotone u32)
__device__ unsigned g_didx[CAP];   // dense candidate original indices
__device__ unsigned g_hist[NHIST]; // coarse histogram of (key-UB)>>13
__device__ unsigned g_total;
__device__ unsigned g_ovf;
__device__ unsigned g_mode;        // 1 => fallback ran; g_du holds winners
__device__ unsigned g_d;           // selected coarse bin
__device__ unsigned g_need2;       // entries still needed from bin g_d

__device__ __forceinline__ unsigned f2u(float f) {
    unsigned b = __float_as_uint(f);
    return (b & 0x80000000u) ? ~b : (b | 0x80000000u);
}
__device__ __forceinline__ float u2f(unsigned u) {
    return __uint_as_float((u & 0x80000000u) ? (u & 0x7fffffffu) : ~u);
}

// ---------------- K1: streaming compaction + coarse histogram (proven) ------
__global__ void __launch_bounds__(512) k_compact(const float* __restrict__ x, int n) {
    __shared__ unsigned s_cnt, s_base;
    __shared__ unsigned skey[BUFCAP];
    __shared__ unsigned sidx[BUFCAP];
    if (threadIdx.x == 0) s_cnt = 0;
    __syncthreads();

    const int n4 = n >> 2;
    const float4* __restrict__ x4 = (const float4*)x;
    const int stride = gridDim.x * blockDim.x;
    int i = blockIdx.x * blockDim.x + threadIdx.x;

    #define PROC4(v, base_) do {                                                  \
        float mx = fmaxf(fmaxf((v).x, (v).y), fmaxf((v).z, (v).w));               \
        unsigned am = __activemask();                                             \
        if (__ballot_sync(am, mx > XGUESS)) {                                     \
            if ((v).x > XGUESS) { unsigned p = atomicAdd(&s_cnt, 1u); if (p < BUFCAP) { skey[p] = f2u((v).x); sidx[p] = (base_) + 0; } } \
            if ((v).y > XGUESS) { unsigned p = atomicAdd(&s_cnt, 1u); if (p < BUFCAP) { skey[p] = f2u((v).y); sidx[p] = (base_) + 1; } } \
            if ((v).z > XGUESS) { unsigned p = atomicAdd(&s_cnt, 1u); if (p < BUFCAP) { skey[p] = f2u((v).z); sidx[p] = (base_) + 2; } } \
            if ((v).w > XGUESS) { unsigned p = atomicAdd(&s_cnt, 1u); if (p < BUFCAP) { skey[p] = f2u((v).w); sidx[p] = (base_) + 3; } } \
        }                                                                         \
    } while (0)

    for (; i + 3 * stride < n4; i += 4 * stride) {
        float4 a = __ldcs(x4 + i);
        float4 b = __ldcs(x4 + i + stride);
        float4 c = __ldcs(x4 + i + 2 * stride);
        float4 d = __ldcs(x4 + i + 3 * stride);
        PROC4(a, (unsigned)i << 2);
        PROC4(b, (unsigned)(i + stride) << 2);
        PROC4(c, (unsigned)(i + 2 * stride) << 2);
        PROC4(d, (unsigned)(i + 3 * stride) << 2);
    }
    for (; i < n4; i += stride) {
        float4 a = __ldcs(x4 + i);
        PROC4(a, (unsigned)i << 2);
    }
    if (blockIdx.x == 0) {       // scalar tail (n not divisible by 4)
        for (int t = (n4 << 2) + threadIdx.x; t < n; t += blockDim.x) {
            float v = x[t];
            if (v > XGUESS) { unsigned p = atomicAdd(&s_cnt, 1u); if (p < BUFCAP) { skey[p] = f2u(v); sidx[p] = (unsigned)t; } }
        }
    }
    __syncthreads();

    unsigned cnt = s_cnt;
    if (cnt > BUFCAP) { if (threadIdx.x == 0) g_ovf = 1u; cnt = BUFCAP; }
    if (threadIdx.x == 0) s_base = atomicAdd(&g_total, cnt);
    __syncthreads();
    const unsigned UB = f2u(XGUESS);
    unsigned base = s_base;
    for (unsigned j = threadIdx.x; j < cnt; j += blockDim.x) {
        unsigned q = base + j;
        unsigned key = skey[j];
        if (q < CAP) { g_du[q] = key; g_didx[q] = sidx[j]; }
        unsigned b = (key - UB) >> 13; if (b > NHIST - 1u) b = NHIST - 1u;
        atomicAdd(&g_hist[b], 1u);
    }
}

// ---- vectorized hierarchical inclusive SUFFIX scan, 1024 threads -----------
template <int NBINS>
__device__ __forceinline__ void suffix_scan_block(unsigned* b, unsigned* wsum) {
    constexpr int NPT = NBINS / 1024;
    constexpr int NV = NPT / 4;
    const unsigned tid = threadIdx.x;
    const unsigned lane = tid & 31u, wid = tid >> 5;
    uint4* b4 = (uint4*)b;
    unsigned v[NPT]; unsigned tsum = 0;
    #pragma unroll
    for (int q = 0; q < NV; q++) {
        uint4 t4 = b4[tid * NV + q];
        v[q*4+0]=t4.x; v[q*4+1]=t4.y; v[q*4+2]=t4.z; v[q*4+3]=t4.w;
    }
    #pragma unroll
    for (int k = 0; k < NPT; k++) tsum += v[k];
    unsigned inc = tsum;
    #pragma unroll
    for (int d = 1; d < 32; d <<= 1) {
        unsigned o = __shfl_down_sync(0xffffffffu, inc, d);
        if (lane + d < 32) inc += o;
    }
    if (lane == 0) wsum[wid] = inc;
    __syncthreads();
    if (wid == 0) {
        unsigned w = wsum[lane];
        unsigned wi = w;
        #pragma unroll
        for (int d = 1; d < 32; d <<= 1) {
            unsigned o = __shfl_down_sync(0xffffffffu, wi, d);
            if (lane + d < 32) wi += o;
        }
        wsum[lane] = wi - w;                 // sum of warps after this warp
    }
    __syncthreads();
    unsigned acc = wsum[wid] + (inc - tsum);
    #pragma unroll
    for (int k = NPT - 1; k >= 0; k--) { acc += v[k]; v[k] = acc; }
    #pragma unroll
    for (int q = 0; q < NV; q++)
        b4[tid * NV + q] = make_uint4(v[q*4+0], v[q*4+1], v[q*4+2], v[q*4+3]);
    __syncthreads();
}

// ---- vectorized hierarchical EXCLUSIVE scan over NB bins, 1024 threads -----
__device__ __forceinline__ void excl_scan_nb(unsigned* b, unsigned* wsum) {
    constexpr int NPT = NB / 1024;      // 8
    constexpr int NV = NPT / 4;         // 2
    const unsigned tid = threadIdx.x;
    const unsigned lane = tid & 31u, wid = tid >> 5;
    uint4* b4 = (uint4*)b;
    unsigned v[NPT], pre[NPT]; unsigned tsum = 0;
    #pragma unroll
    for (int q = 0; q < NV; q++) {
        uint4 t4 = b4[tid * NV + q];
        v[q*4+0]=t4.x; v[q*4+1]=t4.y; v[q*4+2]=t4.z; v[q*4+3]=t4.w;
    }
    #pragma unroll
    for (int k = 0; k < NPT; k++) { pre[k] = tsum; tsum += v[k]; }
    unsigned inc = tsum;
    #pragma unroll
    for (int d = 1; d < 32; d <<= 1) {
        unsigned o = __shfl_up_sync(0xffffffffu, inc, d);
        if (lane >= (unsigned)d) inc += o;
    }
    if (lane == 31) wsum[wid] = inc;
    __syncthreads();
    if (wid == 0) {
        unsigned w = wsum[lane];
        unsigned wi = w;
        #pragma unroll
        for (int d = 1; d < 32; d <<= 1) {
            unsigned o = __shfl_up_sync(0xffffffffu, wi, d);
            if (lane >= (unsigned)d) wi += o;
        }
        wsum[lane] = wi - w;
    }
    __syncthreads();
    unsigned base = wsum[wid] + (inc - tsum);
    #pragma unroll
    for (int q = 0; q < NV; q++)
        b4[tid * NV + q] = make_uint4(base+pre[q*4+0], base+pre[q*4+1],
                                      base+pre[q*4+2], base+pre[q*4+3]);
    __syncthreads();
}

// ---------------- K2: prep (coarse scan) + exact fallback when triggered ----
__global__ void __launch_bounds__(FT) k_prep(const float* __restrict__ x, int n) {
    __shared__ unsigned bins[NHIST];
    __shared__ unsigned sh_d, wsum[32];
    const unsigned tid = threadIdx.x;

    unsigned tot = g_total;
    bool need_fb = !((g_ovf == 0u) && tot >= (unsigned)KSEL && tot <= (unsigned)SMEMCAP
                     && (g_hist[NHIST - 1] < (unsigned)KSEL));

    if (!need_fb) {
        // coarse suffix scan over g_hist; publish d / need2
        for (unsigned t = tid; t < NHIST; t += FT) bins[t] = g_hist[t];
        __syncthreads();
        suffix_scan_block<NHIST>(bins, wsum);
        __shared__ unsigned sh_ab;
        for (unsigned t = tid; t < NHIST; t += FT) {
            unsigned nxt = (t + 1 < NHIST) ? bins[t + 1] : 0;
            if (bins[t] >= (unsigned)KSEL && nxt < (unsigned)KSEL) { sh_d = t; sh_ab = nxt; }
        }
        __syncthreads();
        unsigned d = sh_d, aboveBin = sh_ab;
        unsigned cnt_d = bins[d] - aboveBin;
        if (cnt_d > (unsigned)EQB) need_fb = true;
        else if (tid == 0) { g_d = d; g_need2 = (unsigned)KSEL - aboveBin; }
        __syncthreads();
    }
    if (!need_fb) return;

    // ===== exact full-input fallback (never runs on sane inputs) ============
    unsigned prefix = 0, prefmask = 0, need = KSEL;
    const int vsh[3] = { 21, 10, 0 };
    const int vwd[3] = { 11, 11, 10 };
    for (int r = 0; r < 3; r++) {
        const int sh = vsh[r];
        const int nb = 1 << vwd[r];
        for (int t = tid; t < nb; t += FT) bins[t] = 0;
        __syncthreads();
        for (int i = tid; i < n; i += FT) {
            unsigned u = f2u(x[i]);
            if ((u & prefmask) == prefix) {
                unsigned b = (u >> sh) & (unsigned)(nb - 1);
                unsigned am = __activemask();
                unsigned peers = __match_any_sync(am, b);
                if ((tid & 31u) == (unsigned)(__ffs(peers) - 1))
                    atomicAdd(&bins[b], (unsigned)__popc(peers));
            }
        }
        __syncthreads();
        for (int d2 = 1; d2 < nb; d2 <<= 1) {      // suffix Hillis-Steele
            unsigned t0 = tid, t1 = tid + FT;
            unsigned a0 = (t0 < (unsigned)nb && t0 + d2 < (unsigned)nb) ? bins[t0 + d2] : 0;
            unsigned a1 = (t1 < (unsigned)nb && t1 + d2 < (unsigned)nb) ? bins[t1 + d2] : 0;
            __syncthreads();
            if (t0 < (unsigned)nb) bins[t0] += a0;
            if (t1 < (unsigned)nb) bins[t1] += a1;
            __syncthreads();
        }
        for (int t = tid; t < nb; t += FT) {
            unsigned nxt = (t + 1 < nb) ? bins[t + 1] : 0;
            if (bins[t] >= need && nxt < need) sh_d = (unsigned)t;
        }
        __syncthreads();
        unsigned d2 = sh_d;
        unsigned above = (d2 + 1 < (unsigned)nb) ? bins[d2 + 1] : 0;
        __syncthreads();
        need -= above;
        prefix |= d2 << sh;
        prefmask |= ((unsigned)(nb - 1)) << sh;
    }
    const unsigned uTf = prefix;
    const unsigned Rf = need;

    unsigned iprefix = 0, imask = 0, needi = Rf;
    const int ish[3] = { 15, 4, 0 };
    const int iwd[3] = { 11, 11, 4 };
    if (Rf > 0) {
        for (int r = 0; r < 3; r++) {
            const int sh = ish[r];
            const int nb = 1 << iwd[r];
            for (int t = tid; t < nb; t += FT) bins[t] = 0;
            __syncthreads();
            for (int i = tid; i < n; i += FT) {
                unsigned u = f2u(x[i]);
                if (u == uTf && (((unsigned)i & imask) == iprefix))
                    atomicAdd(&bins[((unsigned)i >> sh) & (unsigned)(nb - 1)], 1u);
            }
            __syncthreads();
            for (int d2 = 1; d2 < nb; d2 <<= 1) {  // prefix Hillis-Steele
                unsigned t0 = tid, t1 = tid + FT;
                unsigned a0 = (t0 < (unsigned)nb && t0 >= (unsigned)d2) ? bins[t0 - d2] : 0;
                unsigned a1 = (t1 < (unsigned)nb && t1 >= (unsigned)d2) ? bins[t1 - d2] : 0;
                __syncthreads();
                if (t0 < (unsigned)nb) bins[t0] += a0;
                if (t1 < (unsigned)nb) bins[t1] += a1;
                __syncthreads();
            }
            for (int t = tid; t < nb; t += FT) {
                unsigned prev = (t > 0) ? bins[t - 1] : 0;
                if (bins[t] >= needi && prev < needi) sh_d = (unsigned)t;
            }
            __syncthreads();
            unsigned d2 = sh_d;
            unsigned below = (d2 > 0) ? bins[d2 - 1] : 0;
            __syncthreads();
            needi -= below;
            iprefix |= d2 << sh;
            imask |= ((unsigned)(nb - 1)) << sh;
        }
    }
    if (tid == 0) g_total = 0;
    __syncthreads();
    for (int i = tid; i < n; i += FT) {
        unsigned u = f2u(x[i]);
        bool keep = (u > uTf) || (Rf > 0 && u == uTf && (unsigned)i <= iprefix);
        if (keep) {
            unsigned p = atomicAdd(&g_total, 1u);
            if (p < CAP) { g_du[p] = u; g_didx[p] = (unsigned)i; }
        }
    }
    if (tid == 0) g_mode = 1u;   // g_du now holds exactly the winners
}

// ---------------- K3: gather-bin select + bucket sort + output (lean) -------
__global__ void __launch_bounds__(FT) k_final(float* __restrict__ out) {
    extern __shared__ unsigned long long sm[];
    unsigned long long* dst = sm;                   // DST_N u64 (idx<<32|key)
    unsigned* bcnt = (unsigned*)(dst + DST_N);      // NB u32
    unsigned long long* eqb = (unsigned long long*)(bcnt + NB);  // EQB u64
    __shared__ unsigned s_cnt, wsum[32];
    const unsigned tid = threadIdx.x;
    const unsigned UB = f2u(XGUESS);

    const unsigned mode = g_mode;
    unsigned T = g_total; if (T > (unsigned)SMEMCAP) T = SMEMCAP;

    // register-resident candidate keys (key 0 == invalid slot)
    unsigned uk[NPT_CAND];
    #pragma unroll
    for (int k = 0; k < NPT_CAND; k++) {
        unsigned j = tid + (unsigned)k * FT;
        uk[k] = (j < T) ? g_du[j] : 0u;
    }

    unsigned uT = 0, cut = 0xffffffffu;
    if (mode == 0u) {
        const unsigned d = g_d;
        const unsigned need2 = g_need2;              // >= 1, <= cnt_d <= EQB

        // gather bin-d entries: e = (key<<32) | ~idx  (warp-aggregated)
        if (tid == 0) s_cnt = 0;
        __syncthreads();
        #pragma unroll
        for (int k = 0; k < NPT_CAND; k++) {
            unsigned j = tid + (unsigned)k * FT;
            bool pred = (j < T) && (((uk[k] - UB) >> 13) == d);
            unsigned mask = __ballot_sync(0xffffffffu, pred);
            if (mask) {
                unsigned lane = tid & 31u;
                unsigned leader = (unsigned)(__ffs(mask) - 1);
                unsigned wbase = 0;
                if (lane == leader) wbase = atomicAdd(&s_cnt, (unsigned)__popc(mask));
                wbase = __shfl_sync(0xffffffffu, wbase, leader);
                if (pred) {
                    unsigned pos = wbase + (unsigned)__popc(mask & ((1u << lane) - 1u));
                    if (pos < (unsigned)EQB)
                        eqb[pos] = ((unsigned long long)uk[k] << 32)
                                 | (unsigned long long)(~g_didx[j]);
                }
            }
        }
        __syncthreads();
        unsigned m = s_cnt;                          // == cnt_d <= EQB
        unsigned np2 = 2; while (np2 < m) np2 <<= 1;
        for (unsigned t = tid; t < np2; t += FT)
            if (t >= m) eqb[t] = 0ull;               // pad sorts last (descending)
        __syncthreads();
        for (unsigned k2 = 2; k2 <= np2; k2 <<= 1) { // bitonic sort DESC
            for (unsigned j2 = k2 >> 1; j2 > 0; j2 >>= 1) {
                for (unsigned t = tid; t < np2 / 2; t += FT) {
                    unsigned i2 = ((t & ~(j2 - 1)) << 1) | (t & (j2 - 1));
                    unsigned p2 = i2 | j2;
                    unsigned long long a = eqb[i2], b = eqb[p2];
                    bool up = ((i2 & k2) == 0);
                    if ((a < b) == up) { eqb[i2] = b; eqb[p2] = a; }
                }
                __syncthreads();
            }
        }
        unsigned long long e = eqb[need2 - 1];       // exact boundary entry
        uT = (unsigned)(e >> 32);
        cut = ~(unsigned)e;                          // largest kept idx among ties
        __syncthreads();
    }
    // mode 1: uT=0, cut=~0 — every staged candidate (key>0) is a winner.

    // ---- bucket sort by original index: bucket = idx >> 13
    for (unsigned t = tid; t < NB; t += FT) bcnt[t] = 0;
    __syncthreads();
    #pragma unroll
    for (int k = 0; k < NPT_CAND; k++) {
        unsigned j = tid + (unsigned)k * FT;
        bool vld = (j < T);
        unsigned u = uk[k];
        bool pre = vld && (u >= uT);
        unsigned ix = pre ? g_didx[j] : 0u;
        bool keep = vld && ((u > uT) || (u == uT && ix <= cut));
        if (keep) atomicAdd(&bcnt[ix >> 13], 1u);
    }
    __syncthreads();

    excl_scan_nb(bcnt, wsum);

    #pragma unroll
    for (int k = 0; k < NPT_CAND; k++) {
        unsigned j = tid + (unsigned)k * FT;
        bool vld = (j < T);
        unsigned u = uk[k];
        bool pre = vld && (u >= uT);
        unsigned ix = pre ? g_didx[j] : 0u;
        bool keep = vld && ((u > uT) || (u == uT && ix <= cut));
        if (keep) {
            unsigned r = atomicAdd(&bcnt[ix >> 13], 1u);
            if (r < (unsigned)DST_N)
                dst[r] = ((unsigned long long)ix << 32) | (unsigned long long)u;
        }
    }
    __syncthreads();

    // tiny per-bucket insertion sorts (bucket sizes ~0-6)
    for (unsigned b = tid; b < NB; b += FT) {
        unsigned s0 = (b > 0) ? bcnt[b - 1] : 0;
        unsigned e0 = bcnt[b];
        if (s0 > (unsigned)DST_N) s0 = DST_N;
        if (e0 > (unsigned)DST_N) e0 = DST_N;
        for (unsigned i2 = s0 + 1; i2 < e0; i2++) {
            unsigned long long key = dst[i2];
            unsigned j2 = i2;
            while (j2 > s0 && dst[j2 - 1] > key) { dst[j2] = dst[j2 - 1]; j2--; }
            dst[j2] = key;
        }
    }
    __syncthreads();

    for (unsigned t = tid; t < KSEL; t += FT)
        out[t] = u2f((unsigned)(dst[t] & 0xffffffffu));

    // restore invariants for next graph replay
    for (unsigned t = tid; t < NHIST; t += FT) g_hist[t] = 0;
    if (tid == 0) { g_total = 0; g_ovf = 0; g_mode = 0; }
}

// ---------------- launch ----------------------------------------------------
extern "C" void kernel_launch(void* const* d_in, const int* in_sizes, int n_in,
                              void* d_out, int out_size) {
    const float* x = (const float*)d_in[0];
    int n = in_sizes[0];
    float* out = (float*)d_out;

    cudaFuncSetAttribute(k_final, cudaFuncAttributeMaxDynamicSharedMemorySize, FIN_SMEM);

    k_compact<<<592, 512>>>(x, n);        // 148 SMs x 4 blocks: one wave
    k_prep<<<1, FT>>>(x, n);              // coarse scan (+ exact fallback if needed)
    k_final<<<1, FT, FIN_SMEM>>>(out);    // gather select + bucket sort + output
}

// round 14
// speedup vs baseline: 1.2393x; 1.0866x over previous
#include <cuda_runtime.h>

#define KSEL     5000
#define CAP      65536
#define SMEMCAP  12288
#define FT       1024
#define NPT_CAND 12          // SMEMCAP / FT
#define BUFCAP   2048
#define XGUESS   3.55f
#define NHIST    4096
#define NB       8192
#define EQB      2048
#define DST_N    5120
#define FIN_SMEM (DST_N*8 + NB*4 + EQB*8)   // 90112 bytes

// ---------------- scratch (static device globals; zero-initialized) ---------
__device__ unsigned g_du[CAP];     // dense candidate keys (monotone u32)
__device__ unsigned g_didx[CAP];   // dense candidate original indices
__device__ unsigned g_hist[NHIST]; // coarse histogram of (key-UB)>>13
__device__ unsigned g_total;
__device__ unsigned g_ovf;

__device__ __forceinline__ unsigned f2u(float f) {
    unsigned b = __float_as_uint(f);
    return (b & 0x80000000u) ? ~b : (b | 0x80000000u);
}
__device__ __forceinline__ float u2f(unsigned u) {
    return __uint_as_float((u & 0x80000000u) ? (u & 0x7fffffffu) : ~u);
}

// ---------------- K1: streaming compaction + coarse histogram (proven) ------
__global__ void __launch_bounds__(512) k_compact(const float* __restrict__ x, int n) {
    __shared__ unsigned s_cnt, s_base;
    __shared__ unsigned skey[BUFCAP];
    __shared__ unsigned sidx[BUFCAP];
    if (threadIdx.x == 0) s_cnt = 0;
    __syncthreads();

    const int n4 = n >> 2;
    const float4* __restrict__ x4 = (const float4*)x;
    const int stride = gridDim.x * blockDim.x;
    int i = blockIdx.x * blockDim.x + threadIdx.x;

    #define PROC4(v, base_) do {                                                  \
        float mx = fmaxf(fmaxf((v).x, (v).y), fmaxf((v).z, (v).w));               \
        unsigned am = __activemask();                                             \
        if (__ballot_sync(am, mx > XGUESS)) {                                     \
            if ((v).x > XGUESS) { unsigned p = atomicAdd(&s_cnt, 1u); if (p < BUFCAP) { skey[p] = f2u((v).x); sidx[p] = (base_) + 0; } } \
            if ((v).y > XGUESS) { unsigned p = atomicAdd(&s_cnt, 1u); if (p < BUFCAP) { skey[p] = f2u((v).y); sidx[p] = (base_) + 1; } } \
            if ((v).z > XGUESS) { unsigned p = atomicAdd(&s_cnt, 1u); if (p < BUFCAP) { skey[p] = f2u((v).z); sidx[p] = (base_) + 2; } } \
            if ((v).w > XGUESS) { unsigned p = atomicAdd(&s_cnt, 1u); if (p < BUFCAP) { skey[p] = f2u((v).w); sidx[p] = (base_) + 3; } } \
        }                                                                         \
    } while (0)

    for (; i + 3 * stride < n4; i += 4 * stride) {
        float4 a = __ldcs(x4 + i);
        float4 b = __ldcs(x4 + i + stride);
        float4 c = __ldcs(x4 + i + 2 * stride);
        float4 d = __ldcs(x4 + i + 3 * stride);
        PROC4(a, (unsigned)i << 2);
        PROC4(b, (unsigned)(i + stride) << 2);
        PROC4(c, (unsigned)(i + 2 * stride) << 2);
        PROC4(d, (unsigned)(i + 3 * stride) << 2);
    }
    for (; i < n4; i += stride) {
        float4 a = __ldcs(x4 + i);
        PROC4(a, (unsigned)i << 2);
    }
    if (blockIdx.x == 0) {       // scalar tail (n not divisible by 4)
        for (int t = (n4 << 2) + threadIdx.x; t < n; t += blockDim.x) {
            float v = x[t];
            if (v > XGUESS) { unsigned p = atomicAdd(&s_cnt, 1u); if (p < BUFCAP) { skey[p] = f2u(v); sidx[p] = (unsigned)t; } }
        }
    }
    __syncthreads();

    unsigned cnt = s_cnt;
    if (cnt > BUFCAP) { if (threadIdx.x == 0) g_ovf = 1u; cnt = BUFCAP; }
    if (threadIdx.x == 0) s_base = atomicAdd(&g_total, cnt);
    __syncthreads();
    const unsigned UB = f2u(XGUESS);
    unsigned base = s_base;
    for (unsigned j = threadIdx.x; j < cnt; j += blockDim.x) {
        unsigned q = base + j;
        unsigned key = skey[j];
        if (q < CAP) { g_du[q] = key; g_didx[q] = sidx[j]; }
        unsigned b = (key - UB) >> 13; if (b > NHIST - 1u) b = NHIST - 1u;
        atomicAdd(&g_hist[b], 1u);
    }
}

// ---- vectorized hierarchical inclusive SUFFIX scan, 1024 threads -----------
template <int NBINS>
__device__ __forceinline__ void suffix_scan_block(unsigned* b, unsigned* wsum) {
    constexpr int NPT = NBINS / FT;
    constexpr int NV = NPT / 4;
    const unsigned tid = threadIdx.x;
    const unsigned lane = tid & 31u, wid = tid >> 5;
    uint4* b4 = (uint4*)b;
    unsigned v[NPT]; unsigned tsum = 0;
    #pragma unroll
    for (int q = 0; q < NV; q++) {
        uint4 t4 = b4[tid * NV + q];
        v[q*4+0]=t4.x; v[q*4+1]=t4.y; v[q*4+2]=t4.z; v[q*4+3]=t4.w;
    }
    #pragma unroll
    for (int k = 0; k < NPT; k++) tsum += v[k];
    unsigned inc = tsum;
    #pragma unroll
    for (int d = 1; d < 32; d <<= 1) {
        unsigned o = __shfl_down_sync(0xffffffffu, inc, d);
        if (lane + d < 32) inc += o;
    }
    if (lane == 0) wsum[wid] = inc;
    __syncthreads();
    if (wid == 0) {
        unsigned w = wsum[lane];
        unsigned wi = w;
        #pragma unroll
        for (int d = 1; d < 32; d <<= 1) {
            unsigned o = __shfl_down_sync(0xffffffffu, wi, d);
            if (lane + d < 32) wi += o;
        }
        wsum[lane] = wi - w;                 // sum of warps after this warp
    }
    __syncthreads();
    unsigned acc = wsum[wid] + (inc - tsum);
    #pragma unroll
    for (int k = NPT - 1; k >= 0; k--) { acc += v[k]; v[k] = acc; }
    #pragma unroll
    for (int q = 0; q < NV; q++)
        b4[tid * NV + q] = make_uint4(v[q*4+0], v[q*4+1], v[q*4+2], v[q*4+3]);
    __syncthreads();
}

// ---- vectorized hierarchical EXCLUSIVE scan over NB bins, 1024 threads -----
__device__ __forceinline__ void excl_scan_nb(unsigned* b, unsigned* wsum) {
    constexpr int NPT = NB / FT;        // 8
    constexpr int NV = NPT / 4;         // 2
    const unsigned tid = threadIdx.x;
    const unsigned lane = tid & 31u, wid = tid >> 5;
    uint4* b4 = (uint4*)b;
    unsigned v[NPT], pre[NPT]; unsigned tsum = 0;
    #pragma unroll
    for (int q = 0; q < NV; q++) {
        uint4 t4 = b4[tid * NV + q];
        v[q*4+0]=t4.x; v[q*4+1]=t4.y; v[q*4+2]=t4.z; v[q*4+3]=t4.w;
    }
    #pragma unroll
    for (int k = 0; k < NPT; k++) { pre[k] = tsum; tsum += v[k]; }
    unsigned inc = tsum;
    #pragma unroll
    for (int d = 1; d < 32; d <<= 1) {
        unsigned o = __shfl_up_sync(0xffffffffu, inc, d);
        if (lane >= (unsigned)d) inc += o;
    }
    if (lane == 31) wsum[wid] = inc;
    __syncthreads();
    if (wid == 0) {
        unsigned w = wsum[lane];
        unsigned wi = w;
        #pragma unroll
        for (int d = 1; d < 32; d <<= 1) {
            unsigned o = __shfl_up_sync(0xffffffffu, wi, d);
            if (lane >= (unsigned)d) wi += o;
        }
        wsum[lane] = wi - w;
    }
    __syncthreads();
    unsigned base = wsum[wid] + (inc - tsum);
    #pragma unroll
    for (int q = 0; q < NV; q++)
        b4[tid * NV + q] = make_uint4(base+pre[q*4+0], base+pre[q*4+1],
                                      base+pre[q*4+2], base+pre[q*4+3]);
    __syncthreads();
}

// ---------------- K2: everything after the stream, one block ----------------
__global__ void __launch_bounds__(FT, 1) k_final(const float* __restrict__ x, int n,
                                                 float* __restrict__ out) {
    extern __shared__ unsigned long long sm[];
    unsigned long long* dst = sm;                   // DST_N u64 (idx<<32|key)
    unsigned* bcnt = (unsigned*)(dst + DST_N);      // NB u32 (scan bins / buckets)
    unsigned long long* eqb = (unsigned long long*)(bcnt + NB);  // EQB u64
    __shared__ unsigned sh_d, sh_ab, s_cnt, wsum[32];
    const unsigned tid = threadIdx.x;
    const unsigned UB = f2u(XGUESS);

    unsigned tot = g_total;
    bool need_fb = !((g_ovf == 0u) && tot >= (unsigned)KSEL && tot <= (unsigned)SMEMCAP
                     && (g_hist[NHIST - 1] < (unsigned)KSEL));
    unsigned T = tot > (unsigned)SMEMCAP ? (unsigned)SMEMCAP : tot;

    // register-resident candidates: keys AND indices (one full-MLP burst)
    unsigned uk[NPT_CAND], ui[NPT_CAND];
    #pragma unroll
    for (int k = 0; k < NPT_CAND; k++) {
        unsigned j = tid + (unsigned)k * FT;
        bool vld = (j < T);
        uk[k] = vld ? g_du[j] : 0u;     // key 0 is never kept
        ui[k] = vld ? g_didx[j] : 0u;
    }

    unsigned uT = 0, cut = 0xffffffffu;
    if (!need_fb) {
        // ---- coarse suffix scan over g_hist (4096 bins, in bcnt region)
        for (unsigned t = tid; t < NHIST; t += FT) bcnt[t] = g_hist[t];
        __syncthreads();
        suffix_scan_block<NHIST>(bcnt, wsum);
        for (unsigned t = tid; t < NHIST; t += FT) {
            unsigned nxt = (t + 1 < NHIST) ? bcnt[t + 1] : 0;
            if (bcnt[t] >= (unsigned)KSEL && nxt < (unsigned)KSEL) { sh_d = t; sh_ab = nxt; }
        }
        __syncthreads();
        const unsigned d = sh_d;
        const unsigned need2 = (unsigned)KSEL - sh_ab;   // >= 1
        const unsigned cnt_d = bcnt[d] - sh_ab;
        __syncthreads();

        if (cnt_d > (unsigned)EQB) {
            need_fb = true;
        } else {
            // ---- gather bin-d entries: e = (key<<32) | ~idx (warp-aggregated)
            if (tid == 0) s_cnt = 0;
            __syncthreads();
            #pragma unroll
            for (int k = 0; k < NPT_CAND; k++) {
                bool pred = (((uk[k] - UB) >> 13) == d) && (uk[k] != 0u);
                unsigned mask = __ballot_sync(0xffffffffu, pred);
                if (mask) {
                    unsigned lane = tid & 31u;
                    unsigned leader = (unsigned)(__ffs(mask) - 1);
                    unsigned wbase = 0;
                    if (lane == leader) wbase = atomicAdd(&s_cnt, (unsigned)__popc(mask));
                    wbase = __shfl_sync(0xffffffffu, wbase, leader);
                    if (pred) {
                        unsigned pos = wbase + (unsigned)__popc(mask & ((1u << lane) - 1u));
                        if (pos < (unsigned)EQB)
                            eqb[pos] = ((unsigned long long)uk[k] << 32)
                                     | (unsigned long long)(~ui[k]);
                    }
                }
            }
            __syncthreads();
            unsigned m = s_cnt;                          // == cnt_d <= EQB
            unsigned np2 = 2; while (np2 < m) np2 <<= 1;
            for (unsigned t = tid; t < np2; t += FT)
                if (t >= m) eqb[t] = 0ull;               // pad sorts last (desc)
            __syncthreads();
            for (unsigned k2 = 2; k2 <= np2; k2 <<= 1) { // bitonic sort DESC
                for (unsigned j2 = k2 >> 1; j2 > 0; j2 >>= 1) {
                    for (unsigned t = tid; t < np2 / 2; t += FT) {
                        unsigned i2 = ((t & ~(j2 - 1)) << 1) | (t & (j2 - 1));
                        unsigned p2 = i2 | j2;
                        unsigned long long a = eqb[i2], b = eqb[p2];
                        bool up = ((i2 & k2) == 0);
                        if ((a < b) == up) { eqb[i2] = b; eqb[p2] = a; }
                    }
                    __syncthreads();
                }
            }
            unsigned long long e = eqb[need2 - 1];       // exact boundary entry
            uT = (unsigned)(e >> 32);
            cut = ~(unsigned)e;                          // largest kept tie idx
            __syncthreads();
        }
    }

    if (need_fb) {
        // ===== exact full-input fallback (cold; never on sane inputs) ========
        unsigned* bins = bcnt;
        unsigned prefix = 0, prefmask = 0, need = KSEL;
        const int vsh[3] = { 21, 10, 0 };
        const int vwd[3] = { 11, 11, 10 };
        for (int r = 0; r < 3; r++) {
            const int sh = vsh[r];
            const int nb = 1 << vwd[r];
            for (int t = tid; t < nb; t += FT) bins[t] = 0;
            __syncthreads();
            for (int i = tid; i < n; i += FT) {
                unsigned u = f2u(x[i]);
                if ((u & prefmask) == prefix) {
                    unsigned b = (u >> sh) & (unsigned)(nb - 1);
                    unsigned am = __activemask();
                    unsigned peers = __match_any_sync(am, b);
                    if ((tid & 31u) == (unsigned)(__ffs(peers) - 1))
                        atomicAdd(&bins[b], (unsigned)__popc(peers));
                }
            }
            __syncthreads();
            for (int d2 = 1; d2 < nb; d2 <<= 1) {      // suffix Hillis-Steele
                unsigned t0 = tid, t1 = tid + FT;
                unsigned a0 = (t0 < (unsigned)nb && t0 + d2 < (unsigned)nb) ? bins[t0 + d2] : 0;
                unsigned a1 = (t1 < (unsigned)nb && t1 + d2 < (unsigned)nb) ? bins[t1 + d2] : 0;
                __syncthreads();
                if (t0 < (unsigned)nb) bins[t0] += a0;
                if (t1 < (unsigned)nb) bins[t1] += a1;
                __syncthreads();
            }
            for (int t = tid; t < nb; t += FT) {
                unsigned nxt = (t + 1 < nb) ? bins[t + 1] : 0;
                if (bins[t] >= need && nxt < need) sh_d = (unsigned)t;
            }
            __syncthreads();
            unsigned d2 = sh_d;
            unsigned above = (d2 + 1 < (unsigned)nb) ? bins[d2 + 1] : 0;
            __syncthreads();
            need -= above;
            prefix |= d2 << sh;
            prefmask |= ((unsigned)(nb - 1)) << sh;
        }
        const unsigned uTf = prefix;
        const unsigned Rf = need;

        unsigned iprefix = 0, imask = 0, needi = Rf;
        const int ish[3] = { 15, 4, 0 };
        const int iwd[3] = { 11, 11, 4 };
        if (Rf > 0) {
            for (int r = 0; r < 3; r++) {
                const int sh = ish[r];
                const int nb = 1 << iwd[r];
                for (int t = tid; t < nb; t += FT) bins[t] = 0;
                __syncthreads();
                for (int i = tid; i < n; i += FT) {
                    unsigned u = f2u(x[i]);
                    if (u == uTf && (((unsigned)i & imask) == iprefix))
                        atomicAdd(&bins[((unsigned)i >> sh) & (unsigned)(nb - 1)], 1u);
                }
                __syncthreads();
                for (int d2 = 1; d2 < nb; d2 <<= 1) {  // prefix Hillis-Steele
                    unsigned t0 = tid, t1 = tid + FT;
                    unsigned a0 = (t0 < (unsigned)nb && t0 >= (unsigned)d2) ? bins[t0 - d2] : 0;
                    unsigned a1 = (t1 < (unsigned)nb && t1 >= (unsigned)d2) ? bins[t1 - d2] : 0;
                    __syncthreads();
                    if (t0 < (unsigned)nb) bins[t0] += a0;
                    if (t1 < (unsigned)nb) bins[t1] += a1;
                    __syncthreads();
                }
                for (int t = tid; t < nb; t += FT) {
                    unsigned prev = (t > 0) ? bins[t - 1] : 0;
                    if (bins[t] >= needi && prev < needi) sh_d = (unsigned)t;
                }
                __syncthreads();
                unsigned d2 = sh_d;
                unsigned below = (d2 > 0) ? bins[d2 - 1] : 0;
                __syncthreads();
                needi -= below;
                iprefix |= d2 << sh;
                imask |= ((unsigned)(nb - 1)) << sh;
            }
        }
        if (tid == 0) g_total = 0;
        __syncthreads();
        for (int i = tid; i < n; i += FT) {
            unsigned u = f2u(x[i]);
            bool keep = (u > uTf) || (Rf > 0 && u == uTf && (unsigned)i <= iprefix);
            if (keep) {
                unsigned p = atomicAdd(&g_total, 1u);
                if (p < CAP) { g_du[p] = u; g_didx[p] = (unsigned)i; }
            }
        }
        __syncthreads();
        T = g_total; if (T > (unsigned)SMEMCAP) T = SMEMCAP;   // == KSEL
        #pragma unroll
        for (int k = 0; k < NPT_CAND; k++) {
            unsigned j = tid + (unsigned)k * FT;
            bool vld = (j < T);
            uk[k] = vld ? g_du[j] : 0u;
            ui[k] = vld ? g_didx[j] : 0u;
        }
        uT = 0; cut = 0xffffffffu;       // every staged candidate is a winner
        __syncthreads();
    }

    // ---- bucket sort by original index: bucket = idx >> 13
    for (unsigned t = tid; t < NB; t += FT) bcnt[t] = 0;
    __syncthreads();
    #pragma unroll
    for (int k = 0; k < NPT_CAND; k++) {
        unsigned u = uk[k];
        bool keep = (u > uT) || (u == uT && u != 0u && ui[k] <= cut);
        if (keep) atomicAdd(&bcnt[ui[k] >> 13], 1u);
    }
    __syncthreads();

    excl_scan_nb(bcnt, wsum);

    #pragma unroll
    for (int k = 0; k < NPT_CAND; k++) {
        unsigned u = uk[k];
        bool keep = (u > uT) || (u == uT && u != 0u && ui[k] <= cut);
        if (keep) {
            unsigned r = atomicAdd(&bcnt[ui[k] >> 13], 1u);
            if (r < (unsigned)DST_N)
                dst[r] = ((unsigned long long)ui[k] << 32) | (unsigned long long)u;
        }
    }
    __syncthreads();

    // tiny per-bucket insertion sorts (bucket sizes ~0-6)
    for (unsigned b = tid; b < NB; b += FT) {
        unsigned s0 = (b > 0) ? bcnt[b - 1] : 0;
        unsigned e0 = bcnt[b];
        if (s0 > (unsigned)DST_N) s0 = DST_N;
        if (e0 > (unsigned)DST_N) e0 = DST_N;
        for (unsigned i2 = s0 + 1; i2 < e0; i2++) {
            unsigned long long key = dst[i2];
            unsigned j2 = i2;
            while (j2 > s0 && dst[j2 - 1] > key) { dst[j2] = dst[j2 - 1]; j2--; }
            dst[j2] = key;
        }
    }
    __syncthreads();

    for (unsigned t = tid; t < KSEL; t += FT)
        out[t] = u2f((unsigned)(dst[t] & 0xffffffffu));

    // restore invariants for next graph replay
    for (unsigned t = tid; t < NHIST; t += FT) g_hist[t] = 0;
    if (tid == 0) { g_total = 0; g_ovf = 0; }
}

// ---------------- launch ----------------------------------------------------
extern "C" void kernel_launch(void* const* d_in, const int* in_sizes, int n_in,
                              void* d_out, int out_size) {
    const float* x = (const float*)d_in[0];
    int n = in_sizes[0];
    float* out = (float*)d_out;

    cudaFuncSetAttribute(k_final, cudaFuncAttributeMaxDynamicSharedMemorySize, FIN_SMEM);

    k_compact<<<592, 512>>>(x, n);             // 148 SMs x 4 blocks: one wave
    k_final<<<1, FT, FIN_SMEM>>>(x, n, out);   // everything else, one block
}

// round 15
// speedup vs baseline: 1.2923x; 1.0428x over previous
#include <cuda_runtime.h>

#define KSEL     5000
#define CAP      65536
#define SMEMCAP  8192
#define FT       1024
#define NPT_CAND 8           // SMEMCAP / FT
#define BUFCAP   2048
#define XGUESS   3.65f
#define NHIST    4096
#define NB       8192
#define EQB      2048
#define DST_N    5120
#define FIN_SMEM (DST_N*8 + NB*4 + EQB*8)   // 90112 bytes

// ---------------- scratch (static device globals; zero-initialized) ---------
__device__ unsigned g_du[CAP];     // dense candidate keys (monotone u32)
__device__ unsigned g_didx[CAP];   // dense candidate original indices
__device__ unsigned g_hist[NHIST]; // coarse histogram of (key-UB)>>13
__device__ unsigned g_total;
__device__ unsigned g_ovf;

__device__ __forceinline__ unsigned f2u(float f) {
    unsigned b = __float_as_uint(f);
    return (b & 0x80000000u) ? ~b : (b | 0x80000000u);
}
__device__ __forceinline__ float u2f(unsigned u) {
    return __uint_as_float((u & 0x80000000u) ? (u & 0x7fffffffu) : ~u);
}

// ---------------- K1: streaming compaction + coarse histogram (proven) ------
__global__ void __launch_bounds__(512) k_compact(const float* __restrict__ x, int n) {
    __shared__ unsigned s_cnt, s_base;
    __shared__ unsigned skey[BUFCAP];
    __shared__ unsigned sidx[BUFCAP];
    if (threadIdx.x == 0) s_cnt = 0;
    __syncthreads();

    const int n4 = n >> 2;
    const float4* __restrict__ x4 = (const float4*)x;
    const int stride = gridDim.x * blockDim.x;
    int i = blockIdx.x * blockDim.x + threadIdx.x;

    #define PROC4(v, base_) do {                                                  \
        float mx = fmaxf(fmaxf((v).x, (v).y), fmaxf((v).z, (v).w));               \
        unsigned am = __activemask();                                             \
        if (__ballot_sync(am, mx > XGUESS)) {                                     \
            if ((v).x > XGUESS) { unsigned p = atomicAdd(&s_cnt, 1u); if (p < BUFCAP) { skey[p] = f2u((v).x); sidx[p] = (base_) + 0; } } \
            if ((v).y > XGUESS) { unsigned p = atomicAdd(&s_cnt, 1u); if (p < BUFCAP) { skey[p] = f2u((v).y); sidx[p] = (base_) + 1; } } \
            if ((v).z > XGUESS) { unsigned p = atomicAdd(&s_cnt, 1u); if (p < BUFCAP) { skey[p] = f2u((v).z); sidx[p] = (base_) + 2; } } \
            if ((v).w > XGUESS) { unsigned p = atomicAdd(&s_cnt, 1u); if (p < BUFCAP) { skey[p] = f2u((v).w); sidx[p] = (base_) + 3; } } \
        }                                                                         \
    } while (0)

    for (; i + 3 * stride < n4; i += 4 * stride) {
        float4 a = __ldcs(x4 + i);
        float4 b = __ldcs(x4 + i + stride);
        float4 c = __ldcs(x4 + i + 2 * stride);
        float4 d = __ldcs(x4 + i + 3 * stride);
        PROC4(a, (unsigned)i << 2);
        PROC4(b, (unsigned)(i + stride) << 2);
        PROC4(c, (unsigned)(i + 2 * stride) << 2);
        PROC4(d, (unsigned)(i + 3 * stride) << 2);
    }
    for (; i < n4; i += stride) {
        float4 a = __ldcs(x4 + i);
        PROC4(a, (unsigned)i << 2);
    }
    if (blockIdx.x == 0) {       // scalar tail (n not divisible by 4)
        for (int t = (n4 << 2) + threadIdx.x; t < n; t += blockDim.x) {
            float v = x[t];
            if (v > XGUESS) { unsigned p = atomicAdd(&s_cnt, 1u); if (p < BUFCAP) { skey[p] = f2u(v); sidx[p] = (unsigned)t; } }
        }
    }
    __syncthreads();

    unsigned cnt = s_cnt;
    if (cnt > BUFCAP) { if (threadIdx.x == 0) g_ovf = 1u; cnt = BUFCAP; }
    if (threadIdx.x == 0) s_base = atomicAdd(&g_total, cnt);
    __syncthreads();
    const unsigned UB = f2u(XGUESS);
    unsigned base = s_base;
    for (unsigned j = threadIdx.x; j < cnt; j += blockDim.x) {
        unsigned q = base + j;
        unsigned key = skey[j];
        if (q < CAP) { g_du[q] = key; g_didx[q] = sidx[j]; }
        unsigned b = (key - UB) >> 13; if (b > NHIST - 1u) b = NHIST - 1u;
        atomicAdd(&g_hist[b], 1u);
    }
}

// ---- vectorized hierarchical inclusive SUFFIX scan, 1024 threads -----------
template <int NBINS>
__device__ __forceinline__ void suffix_scan_block(unsigned* b, unsigned* wsum) {
    constexpr int NPT = NBINS / FT;
    constexpr int NV = NPT / 4;
    const unsigned tid = threadIdx.x;
    const unsigned lane = tid & 31u, wid = tid >> 5;
    uint4* b4 = (uint4*)b;
    unsigned v[NPT]; unsigned tsum = 0;
    #pragma unroll
    for (int q = 0; q < NV; q++) {
        uint4 t4 = b4[tid * NV + q];
        v[q*4+0]=t4.x; v[q*4+1]=t4.y; v[q*4+2]=t4.z; v[q*4+3]=t4.w;
    }
    #pragma unroll
    for (int k = 0; k < NPT; k++) tsum += v[k];
    unsigned inc = tsum;
    #pragma unroll
    for (int d = 1; d < 32; d <<= 1) {
        unsigned o = __shfl_down_sync(0xffffffffu, inc, d);
        if (lane + d < 32) inc += o;
    }
    if (lane == 0) wsum[wid] = inc;
    __syncthreads();
    if (wid == 0) {
        unsigned w = wsum[lane];
        unsigned wi = w;
        #pragma unroll
        for (int d = 1; d < 32; d <<= 1) {
            unsigned o = __shfl_down_sync(0xffffffffu, wi, d);
            if (lane + d < 32) wi += o;
        }
        wsum[lane] = wi - w;                 // sum of warps after this warp
    }
    __syncthreads();
    unsigned acc = wsum[wid] + (inc - tsum);
    #pragma unroll
    for (int k = NPT - 1; k >= 0; k--) { acc += v[k]; v[k] = acc; }
    #pragma unroll
    for (int q = 0; q < NV; q++)
        b4[tid * NV + q] = make_uint4(v[q*4+0], v[q*4+1], v[q*4+2], v[q*4+3]);
    __syncthreads();
}

// ---- vectorized hierarchical EXCLUSIVE scan over NB bins, 1024 threads -----
__device__ __forceinline__ void excl_scan_nb(unsigned* b, unsigned* wsum) {
    constexpr int NPT = NB / FT;        // 8
    constexpr int NV = NPT / 4;         // 2
    const unsigned tid = threadIdx.x;
    const unsigned lane = tid & 31u, wid = tid >> 5;
    uint4* b4 = (uint4*)b;
    unsigned v[NPT], pre[NPT]; unsigned tsum = 0;
    #pragma unroll
    for (int q = 0; q < NV; q++) {
        uint4 t4 = b4[tid * NV + q];
        v[q*4+0]=t4.x; v[q*4+1]=t4.y; v[q*4+2]=t4.z; v[q*4+3]=t4.w;
    }
    #pragma unroll
    for (int k = 0; k < NPT; k++) { pre[k] = tsum; tsum += v[k]; }
    unsigned inc = tsum;
    #pragma unroll
    for (int d = 1; d < 32; d <<= 1) {
        unsigned o = __shfl_up_sync(0xffffffffu, inc, d);
        if (lane >= (unsigned)d) inc += o;
    }
    if (lane == 31) wsum[wid] = inc;
    __syncthreads();
    if (wid == 0) {
        unsigned w = wsum[lane];
        unsigned wi = w;
        #pragma unroll
        for (int d = 1; d < 32; d <<= 1) {
            unsigned o = __shfl_up_sync(0xffffffffu, wi, d);
            if (lane >= (unsigned)d) wi += o;
        }
        wsum[lane] = wi - w;
    }
    __syncthreads();
    unsigned base = wsum[wid] + (inc - tsum);
    #pragma unroll
    for (int q = 0; q < NV; q++)
        b4[tid * NV + q] = make_uint4(base+pre[q*4+0], base+pre[q*4+1],
                                      base+pre[q*4+2], base+pre[q*4+3]);
    __syncthreads();
}

// ---------------- K2: everything after the stream, one block ----------------
__global__ void __launch_bounds__(FT, 1) k_final(const float* __restrict__ x, int n,
                                                 float* __restrict__ out) {
    extern __shared__ unsigned long long sm[];
    unsigned long long* dst = sm;                   // DST_N u64 (idx<<32|key)
    unsigned* bcnt = (unsigned*)(dst + DST_N);      // NB u32 (scan bins / buckets)
    unsigned long long* eqb = (unsigned long long*)(bcnt + NB);  // EQB u64
    __shared__ unsigned sh_d, sh_ab, s_cnt, wsum[32];
    const unsigned tid = threadIdx.x;
    const unsigned UB = f2u(XGUESS);

    unsigned tot = g_total;
    bool need_fb = !((g_ovf == 0u) && tot >= (unsigned)KSEL && tot <= (unsigned)SMEMCAP
                     && (g_hist[NHIST - 1] < (unsigned)KSEL));
    unsigned T = tot > (unsigned)SMEMCAP ? (unsigned)SMEMCAP : tot;

    // register-resident candidates: keys AND indices (one full-MLP burst)
    unsigned uk[NPT_CAND], ui[NPT_CAND];
    #pragma unroll
    for (int k = 0; k < NPT_CAND; k++) {
        unsigned j = tid + (unsigned)k * FT;
        bool vld = (j < T);
        uk[k] = vld ? g_du[j] : 0u;     // key 0 is never kept
        ui[k] = vld ? g_didx[j] : 0u;
    }

    unsigned uT = 0, cut = 0xffffffffu;
    if (!need_fb) {
        // ---- coarse suffix scan over g_hist (4096 bins, in bcnt region)
        for (unsigned t = tid; t < NHIST; t += FT) bcnt[t] = g_hist[t];
        __syncthreads();
        suffix_scan_block<NHIST>(bcnt, wsum);
        for (unsigned t = tid; t < NHIST; t += FT) {
            unsigned nxt = (t + 1 < NHIST) ? bcnt[t + 1] : 0;
            if (bcnt[t] >= (unsigned)KSEL && nxt < (unsigned)KSEL) { sh_d = t; sh_ab = nxt; }
        }
        __syncthreads();
        const unsigned d = sh_d;
        const unsigned need2 = (unsigned)KSEL - sh_ab;   // >= 1
        const unsigned cnt_d = bcnt[d] - sh_ab;
        __syncthreads();

        if (cnt_d > (unsigned)EQB) {
            need_fb = true;
        } else {
            // ---- gather bin-d entries: e = (key<<32) | ~idx (warp-aggregated)
            if (tid == 0) s_cnt = 0;
            __syncthreads();
            #pragma unroll
            for (int k = 0; k < NPT_CAND; k++) {
                bool pred = (((uk[k] - UB) >> 13) == d) && (uk[k] != 0u);
                unsigned mask = __ballot_sync(0xffffffffu, pred);
                if (mask) {
                    unsigned lane = tid & 31u;
                    unsigned leader = (unsigned)(__ffs(mask) - 1);
                    unsigned wbase = 0;
                    if (lane == leader) wbase = atomicAdd(&s_cnt, (unsigned)__popc(mask));
                    wbase = __shfl_sync(0xffffffffu, wbase, leader);
                    if (pred) {
                        unsigned pos = wbase + (unsigned)__popc(mask & ((1u << lane) - 1u));
                        if (pos < (unsigned)EQB)
                            eqb[pos] = ((unsigned long long)uk[k] << 32)
                                     | (unsigned long long)(~ui[k]);
                    }
                }
            }
            __syncthreads();
            unsigned m = s_cnt;                          // == cnt_d <= EQB
            unsigned np2 = 2; while (np2 < m) np2 <<= 1;
            for (unsigned t = tid; t < np2; t += FT)
                if (t >= m) eqb[t] = 0ull;               // pad sorts last (desc)
            __syncthreads();
            if (np2 <= 256u) {
                // warp 0 sorts alone: no block barriers in the phase loop
                if (tid < 32u) {
                    for (unsigned k2 = 2; k2 <= np2; k2 <<= 1) {
                        for (unsigned j2 = k2 >> 1; j2 > 0; j2 >>= 1) {
                            for (unsigned t = tid; t < np2 / 2; t += 32u) {
                                unsigned i2 = ((t & ~(j2 - 1)) << 1) | (t & (j2 - 1));
                                unsigned p2 = i2 | j2;
                                unsigned long long a = eqb[i2], b = eqb[p2];
                                bool up = ((i2 & k2) == 0);
                                if ((a < b) == up) { eqb[i2] = b; eqb[p2] = a; }
                            }
                            __syncwarp();
                        }
                    }
                }
                __syncthreads();
            } else {
                for (unsigned k2 = 2; k2 <= np2; k2 <<= 1) { // block bitonic DESC
                    for (unsigned j2 = k2 >> 1; j2 > 0; j2 >>= 1) {
                        for (unsigned t = tid; t < np2 / 2; t += FT) {
                            unsigned i2 = ((t & ~(j2 - 1)) << 1) | (t & (j2 - 1));
                            unsigned p2 = i2 | j2;
                            unsigned long long a = eqb[i2], b = eqb[p2];
                            bool up = ((i2 & k2) == 0);
                            if ((a < b) == up) { eqb[i2] = b; eqb[p2] = a; }
                        }
                        __syncthreads();
                    }
                }
            }
            unsigned long long e = eqb[need2 - 1];       // exact boundary entry
            uT = (unsigned)(e >> 32);
            cut = ~(unsigned)e;                          // largest kept tie idx
            __syncthreads();
        }
    }

    if (need_fb) {
        // ===== exact full-input fallback (cold; never on sane inputs) ========
        unsigned* bins = bcnt;
        unsigned prefix = 0, prefmask = 0, need = KSEL;
        const int vsh[3] = { 21, 10, 0 };
        const int vwd[3] = { 11, 11, 10 };
        for (int r = 0; r < 3; r++) {
            const int sh = vsh[r];
            const int nb = 1 << vwd[r];
            for (int t = tid; t < nb; t += FT) bins[t] = 0;
            __syncthreads();
            for (int i = tid; i < n; i += FT) {
                unsigned u = f2u(x[i]);
                if ((u & prefmask) == prefix) {
                    unsigned b = (u >> sh) & (unsigned)(nb - 1);
                    unsigned am = __activemask();
                    unsigned peers = __match_any_sync(am, b);
                    if ((tid & 31u) == (unsigned)(__ffs(peers) - 1))
                        atomicAdd(&bins[b], (unsigned)__popc(peers));
                }
            }
            __syncthreads();
            for (int d2 = 1; d2 < nb; d2 <<= 1) {      // suffix Hillis-Steele
                unsigned t0 = tid, t1 = tid + FT;
                unsigned a0 = (t0 < (unsigned)nb && t0 + d2 < (unsigned)nb) ? bins[t0 + d2] : 0;
                unsigned a1 = (t1 < (unsigned)nb && t1 + d2 < (unsigned)nb) ? bins[t1 + d2] : 0;
                __syncthreads();
                if (t0 < (unsigned)nb) bins[t0] += a0;
                if (t1 < (unsigned)nb) bins[t1] += a1;
                __syncthreads();
            }
            for (int t = tid; t < nb; t += FT) {
                unsigned nxt = (t + 1 < nb) ? bins[t + 1] : 0;
                if (bins[t] >= need && nxt < need) sh_d = (unsigned)t;
            }
            __syncthreads();
            unsigned d2 = sh_d;
            unsigned above = (d2 + 1 < (unsigned)nb) ? bins[d2 + 1] : 0;
            __syncthreads();
            need -= above;
            prefix |= d2 << sh;
            prefmask |= ((unsigned)(nb - 1)) << sh;
        }
        const unsigned uTf = prefix;
        const unsigned Rf = need;

        unsigned iprefix = 0, imask = 0, needi = Rf;
        const int ish[3] = { 15, 4, 0 };
        const int iwd[3] = { 11, 11, 4 };
        if (Rf > 0) {
            for (int r = 0; r < 3; r++) {
                const int sh = ish[r];
                const int nb = 1 << iwd[r];
                for (int t = tid; t < nb; t += FT) bins[t] = 0;
                __syncthreads();
                for (int i = tid; i < n; i += FT) {
                    unsigned u = f2u(x[i]);
                    if (u == uTf && (((unsigned)i & imask) == iprefix))
                        atomicAdd(&bins[((unsigned)i >> sh) & (unsigned)(nb - 1)], 1u);
                }
                __syncthreads();
                for (int d2 = 1; d2 < nb; d2 <<= 1) {  // prefix Hillis-Steele
                    unsigned t0 = tid, t1 = tid + FT;
                    unsigned a0 = (t0 < (unsigned)nb && t0 >= (unsigned)d2) ? bins[t0 - d2] : 0;
                    unsigned a1 = (t1 < (unsigned)nb && t1 >= (unsigned)d2) ? bins[t1 - d2] : 0;
                    __syncthreads();
                    if (t0 < (unsigned)nb) bins[t0] += a0;
                    if (t1 < (unsigned)nb) bins[t1] += a1;
                    __syncthreads();
                }
                for (int t = tid; t < nb; t += FT) {
                    unsigned prev = (t > 0) ? bins[t - 1] : 0;
                    if (bins[t] >= needi && prev < needi) sh_d = (unsigned)t;
                }
                __syncthreads();
                unsigned d2 = sh_d;
                unsigned below = (d2 > 0) ? bins[d2 - 1] : 0;
                __syncthreads();
                needi -= below;
                iprefix |= d2 << sh;
                imask |= ((unsigned)(nb - 1)) << sh;
            }
        }
        if (tid == 0) g_total = 0;
        __syncthreads();
        for (int i = tid; i < n; i += FT) {
            unsigned u = f2u(x[i]);
            bool keep = (u > uTf) || (Rf > 0 && u == uTf && (unsigned)i <= iprefix);
            if (keep) {
                unsigned p = atomicAdd(&g_total, 1u);
                if (p < CAP) { g_du[p] = u; g_didx[p] = (unsigned)i; }
            }
        }
        __syncthreads();
        T = g_total; if (T > (unsigned)SMEMCAP) T = SMEMCAP;   // == KSEL
        #pragma unroll
        for (int k = 0; k < NPT_CAND; k++) {
            unsigned j = tid + (unsigned)k * FT;
            bool vld = (j < T);
            uk[k] = vld ? g_du[j] : 0u;
            ui[k] = vld ? g_didx[j] : 0u;
        }
        uT = 0; cut = 0xffffffffu;       // every staged candidate is a winner
        __syncthreads();
    }

    // ---- bucket sort by original index: bucket = idx >> 13
    for (unsigned t = tid; t < NB; t += FT) bcnt[t] = 0;
    __syncthreads();
    #pragma unroll
    for (int k = 0; k < NPT_CAND; k++) {
        unsigned u = uk[k];
        bool keep = (u > uT) || (u == uT && u != 0u && ui[k] <= cut);
        if (keep) atomicAdd(&bcnt[ui[k] >> 13], 1u);
    }
    __syncthreads();

    excl_scan_nb(bcnt, wsum);

    #pragma unroll
    for (int k = 0; k < NPT_CAND; k++) {
        unsigned u = uk[k];
        bool keep = (u > uT) || (u == uT && u != 0u && ui[k] <= cut);
        if (keep) {
            unsigned r = atomicAdd(&bcnt[ui[k] >> 13], 1u);
            if (r < (unsigned)DST_N)
                dst[r] = ((unsigned long long)ui[k] << 32) | (unsigned long long)u;
        }
    }
    __syncthreads();

    // tiny per-bucket insertion sorts (bucket sizes ~0-6)
    for (unsigned b = tid; b < NB; b += FT) {
        unsigned s0 = (b > 0) ? bcnt[b - 1] : 0;
        unsigned e0 = bcnt[b];
        if (s0 > (unsigned)DST_N) s0 = DST_N;
        if (e0 > (unsigned)DST_N) e0 = DST_N;
        for (unsigned i2 = s0 + 1; i2 < e0; i2++) {
            unsigned long long key = dst[i2];
            unsigned j2 = i2;
            while (j2 > s0 && dst[j2 - 1] > key) { dst[j2] = dst[j2 - 1]; j2--; }
            dst[j2] = key;
        }
    }
    __syncthreads();

    for (unsigned t = tid; t < KSEL; t += FT)
        out[t] = u2f((unsigned)(dst[t] & 0xffffffffu));

    // restore invariants for next graph replay
    for (unsigned t = tid; t < NHIST; t += FT) g_hist[t] = 0;
    if (tid == 0) { g_total = 0; g_ovf = 0; }
}

// ---------------- launch ----------------------------------------------------
extern "C" void kernel_launch(void* const* d_in, const int* in_sizes, int n_in,
                              void* d_out, int out_size) {
    const float* x = (const float*)d_in[0];
    int n = in_sizes[0];
    float* out = (float*)d_out;

    cudaFuncSetAttribute(k_final, cudaFuncAttributeMaxDynamicSharedMemorySize, FIN_SMEM);

    k_compact<<<592, 512>>>(x, n);             // 148 SMs x 4 blocks: one wave
    k_final<<<1, FT, FIN_SMEM>>>(x, n, out);   // everything else, one block
}

// round 16
// speedup vs baseline: 1.3567x; 1.0499x over previous
#include <cuda_runtime.h>

#define KSEL     5000
#define CAP      65536
#define SMEMCAP  8192
#define FT       1024
#define NPT_CAND 8           // SMEMCAP / FT
#define BUFCAP   2048
#define XGUESS   3.65f
#define NHIST    4096
#define NB       8192
#define EQB      2048
#define DST_N    5120
#define FIN_SMEM (DST_N*8 + NB*4 + EQB*8)   // 90112 bytes

// ---------------- scratch (static device globals; zero-initialized) ---------
__device__ unsigned g_du[CAP];     // dense candidate keys (monotone u32)
__device__ unsigned g_didx[CAP];   // dense candidate original indices
__device__ unsigned g_hist[NHIST]; // coarse histogram of (key-UB)>>13
__device__ unsigned g_total;
__device__ unsigned g_ovf;

__device__ __forceinline__ unsigned f2u(float f) {
    unsigned b = __float_as_uint(f);
    return (b & 0x80000000u) ? ~b : (b | 0x80000000u);
}
__device__ __forceinline__ float u2f(unsigned u) {
    return __uint_as_float((u & 0x80000000u) ? (u & 0x7fffffffu) : ~u);
}

// ---------------- K1: streaming compaction + coarse histogram (proven) ------
__global__ void __launch_bounds__(512) k_compact(const float* __restrict__ x, int n) {
    __shared__ unsigned s_cnt, s_base;
    __shared__ unsigned skey[BUFCAP];
    __shared__ unsigned sidx[BUFCAP];
    if (threadIdx.x == 0) s_cnt = 0;
    __syncthreads();

    const int n4 = n >> 2;
    const float4* __restrict__ x4 = (const float4*)x;
    const int stride = gridDim.x * blockDim.x;
    int i = blockIdx.x * blockDim.x + threadIdx.x;

    #define PROC4(v, base_) do {                                                  \
        float mx = fmaxf(fmaxf((v).x, (v).y), fmaxf((v).z, (v).w));               \
        unsigned am = __activemask();                                             \
        if (__ballot_sync(am, mx > XGUESS)) {                                     \
            if ((v).x > XGUESS) { unsigned p = atomicAdd(&s_cnt, 1u); if (p < BUFCAP) { skey[p] = f2u((v).x); sidx[p] = (base_) + 0; } } \
            if ((v).y > XGUESS) { unsigned p = atomicAdd(&s_cnt, 1u); if (p < BUFCAP) { skey[p] = f2u((v).y); sidx[p] = (base_) + 1; } } \
            if ((v).z > XGUESS) { unsigned p = atomicAdd(&s_cnt, 1u); if (p < BUFCAP) { skey[p] = f2u((v).z); sidx[p] = (base_) + 2; } } \
            if ((v).w > XGUESS) { unsigned p = atomicAdd(&s_cnt, 1u); if (p < BUFCAP) { skey[p] = f2u((v).w); sidx[p] = (base_) + 3; } } \
        }                                                                         \
    } while (0)

    for (; i + 3 * stride < n4; i += 4 * stride) {
        float4 a = __ldcs(x4 + i);
        float4 b = __ldcs(x4 + i + stride);
        float4 c = __ldcs(x4 + i + 2 * stride);
        float4 d = __ldcs(x4 + i + 3 * stride);
        PROC4(a, (unsigned)i << 2);
        PROC4(b, (unsigned)(i + stride) << 2);
        PROC4(c, (unsigned)(i + 2 * stride) << 2);
        PROC4(d, (unsigned)(i + 3 * stride) << 2);
    }
    for (; i < n4; i += stride) {
        float4 a = __ldcs(x4 + i);
        PROC4(a, (unsigned)i << 2);
    }
    if (blockIdx.x == 0) {       // scalar tail (n not divisible by 4)
        for (int t = (n4 << 2) + threadIdx.x; t < n; t += blockDim.x) {
            float v = x[t];
            if (v > XGUESS) { unsigned p = atomicAdd(&s_cnt, 1u); if (p < BUFCAP) { skey[p] = f2u(v); sidx[p] = (unsigned)t; } }
        }
    }
    __syncthreads();

    unsigned cnt = s_cnt;
    if (cnt > BUFCAP) { if (threadIdx.x == 0) g_ovf = 1u; cnt = BUFCAP; }
    if (threadIdx.x == 0) s_base = atomicAdd(&g_total, cnt);
    __syncthreads();
    const unsigned UB = f2u(XGUESS);
    unsigned base = s_base;
    for (unsigned j = threadIdx.x; j < cnt; j += blockDim.x) {
        unsigned q = base + j;
        unsigned key = skey[j];
        if (q < CAP) { g_du[q] = key; g_didx[q] = sidx[j]; }
        unsigned b = (key - UB) >> 13; if (b > NHIST - 1u) b = NHIST - 1u;
        atomicAdd(&g_hist[b], 1u);
    }
    cudaTriggerProgrammaticLaunchCompletion();
}

// ---- vectorized hierarchical inclusive SUFFIX scan, 1024 threads -----------
template <int NBINS>
__device__ __forceinline__ void suffix_scan_block(unsigned* b, unsigned* wsum) {
    constexpr int NPT = NBINS / FT;
    constexpr int NV = NPT / 4;
    const unsigned tid = threadIdx.x;
    const unsigned lane = tid & 31u, wid = tid >> 5;
    uint4* b4 = (uint4*)b;
    unsigned v[NPT]; unsigned tsum = 0;
    #pragma unroll
    for (int q = 0; q < NV; q++) {
        uint4 t4 = b4[tid * NV + q];
        v[q*4+0]=t4.x; v[q*4+1]=t4.y; v[q*4+2]=t4.z; v[q*4+3]=t4.w;
    }
    #pragma unroll
    for (int k = 0; k < NPT; k++) tsum += v[k];
    unsigned inc = tsum;
    #pragma unroll
    for (int d = 1; d < 32; d <<= 1) {
        unsigned o = __shfl_down_sync(0xffffffffu, inc, d);
        if (lane + d < 32) inc += o;
    }
    if (lane == 0) wsum[wid] = inc;
    __syncthreads();
    if (wid == 0) {
        unsigned w = wsum[lane];
        unsigned wi = w;
        #pragma unroll
        for (int d = 1; d < 32; d <<= 1) {
            unsigned o = __shfl_down_sync(0xffffffffu, wi, d);
            if (lane + d < 32) wi += o;
        }
        wsum[lane] = wi - w;                 // sum of warps after this warp
    }
    __syncthreads();
    unsigned acc = wsum[wid] + (inc - tsum);
    #pragma unroll
    for (int k = NPT - 1; k >= 0; k--) { acc += v[k]; v[k] = acc; }
    #pragma unroll
    for (int q = 0; q < NV; q++)
        b4[tid * NV + q] = make_uint4(v[q*4+0], v[q*4+1], v[q*4+2], v[q*4+3]);
    __syncthreads();
}

// ---- vectorized hierarchical EXCLUSIVE scan over NB bins, 1024 threads -----
__device__ __forceinline__ void excl_scan_nb(unsigned* b, unsigned* wsum) {
    constexpr int NPT = NB / FT;        // 8
    constexpr int NV = NPT / 4;         // 2
    const unsigned tid = threadIdx.x;
    const unsigned lane = tid & 31u, wid = tid >> 5;
    uint4* b4 = (uint4*)b;
    unsigned v[NPT], pre[NPT]; unsigned tsum = 0;
    #pragma unroll
    for (int q = 0; q < NV; q++) {
        uint4 t4 = b4[tid * NV + q];
        v[q*4+0]=t4.x; v[q*4+1]=t4.y; v[q*4+2]=t4.z; v[q*4+3]=t4.w;
    }
    #pragma unroll
    for (int k = 0; k < NPT; k++) { pre[k] = tsum; tsum += v[k]; }
    unsigned inc = tsum;
    #pragma unroll
    for (int d = 1; d < 32; d <<= 1) {
        unsigned o = __shfl_up_sync(0xffffffffu, inc, d);
        if (lane >= (unsigned)d) inc += o;
    }
    if (lane == 31) wsum[wid] = inc;
    __syncthreads();
    if (wid == 0) {
        unsigned w = wsum[lane];
        unsigned wi = w;
        #pragma unroll
        for (int d = 1; d < 32; d <<= 1) {
            unsigned o = __shfl_up_sync(0xffffffffu, wi, d);
            if (lane >= (unsigned)d) wi += o;
        }
        wsum[lane] = wi - w;
    }
    __syncthreads();
    unsigned base = wsum[wid] + (inc - tsum);
    #pragma unroll
    for (int q = 0; q < NV; q++)
        b4[tid * NV + q] = make_uint4(base+pre[q*4+0], base+pre[q*4+1],
                                      base+pre[q*4+2], base+pre[q*4+3]);
    __syncthreads();
}

// ---------------- K2: everything after the stream, one block (PDL) ----------
__global__ void __launch_bounds__(FT, 1) k_final(const float* __restrict__ x, int n,
                                                 float* __restrict__ out) {
    extern __shared__ unsigned long long sm[];
    unsigned long long* dst = sm;                   // DST_N u64 (idx<<32|key)
    unsigned* bcnt = (unsigned*)(dst + DST_N);      // NB u32 (buckets)
    unsigned long long* eqb = (unsigned long long*)(bcnt + NB);  // EQB u64
    unsigned* cbin = (unsigned*)eqb;                // NHIST u32 (coarse bins; reused)
    __shared__ unsigned sh_d, sh_ab, s_cnt, wsum[32];
    const unsigned tid = threadIdx.x;
    const unsigned UB = f2u(XGUESS);

    // ---- independent preamble: zero bucket array while stream still runs
    {
        uint4* b4 = (uint4*)bcnt;
        b4[tid * 2]     = make_uint4(0, 0, 0, 0);
        b4[tid * 2 + 1] = make_uint4(0, 0, 0, 0);
    }
    cudaGridDependencySynchronize();   // wait for k_compact's results

    unsigned tot = g_total;
    bool need_fb = !((g_ovf == 0u) && tot >= (unsigned)KSEL && tot <= (unsigned)SMEMCAP
                     && (g_hist[NHIST - 1] < (unsigned)KSEL));
    unsigned T = tot > (unsigned)SMEMCAP ? (unsigned)SMEMCAP : tot;

    // register-resident candidates: keys AND indices (one full-MLP burst)
    unsigned uk[NPT_CAND], ui[NPT_CAND];
    #pragma unroll
    for (int k = 0; k < NPT_CAND; k++) {
        unsigned j = tid + (unsigned)k * FT;
        bool vld = (j < T);
        uk[k] = vld ? g_du[j] : 0u;     // key 0 is never kept
        ui[k] = vld ? g_didx[j] : 0u;
    }

    unsigned uT = 0, cut = 0xffffffffu;
    if (!need_fb) {
        // ---- coarse suffix scan over g_hist (4096 bins, in cbin/eqb region)
        for (unsigned t = tid; t < NHIST; t += FT) cbin[t] = g_hist[t];
        __syncthreads();
        suffix_scan_block<NHIST>(cbin, wsum);
        for (unsigned t = tid; t < NHIST; t += FT) {
            unsigned nxt = (t + 1 < NHIST) ? cbin[t + 1] : 0;
            if (cbin[t] >= (unsigned)KSEL && nxt < (unsigned)KSEL) { sh_d = t; sh_ab = nxt; }
        }
        __syncthreads();
        const unsigned d = sh_d;
        const unsigned need2 = (unsigned)KSEL - sh_ab;   // >= 1
        const unsigned cnt_d = cbin[d] - sh_ab;
        __syncthreads();                                 // cbin reads done; eqb reusable

        if (cnt_d > (unsigned)EQB) {
            need_fb = true;
        } else {
            // ---- gather bin-d entries: e = (key<<32) | ~idx (warp-aggregated)
            if (tid == 0) s_cnt = 0;
            __syncthreads();
            #pragma unroll
            for (int k = 0; k < NPT_CAND; k++) {
                bool pred = (((uk[k] - UB) >> 13) == d) && (uk[k] != 0u);
                unsigned mask = __ballot_sync(0xffffffffu, pred);
                if (mask) {
                    unsigned lane = tid & 31u;
                    unsigned leader = (unsigned)(__ffs(mask) - 1);
                    unsigned wbase = 0;
                    if (lane == leader) wbase = atomicAdd(&s_cnt, (unsigned)__popc(mask));
                    wbase = __shfl_sync(0xffffffffu, wbase, leader);
                    if (pred) {
                        unsigned pos = wbase + (unsigned)__popc(mask & ((1u << lane) - 1u));
                        if (pos < (unsigned)EQB)
                            eqb[pos] = ((unsigned long long)uk[k] << 32)
                                     | (unsigned long long)(~ui[k]);
                    }
                }
            }
            __syncthreads();
            unsigned m = s_cnt;                          // == cnt_d <= EQB
            unsigned np2 = 2; while (np2 < m) np2 <<= 1;
            for (unsigned t = tid; t < np2; t += FT)
                if (t >= m) eqb[t] = 0ull;               // pad sorts last (desc)
            __syncthreads();
            if (np2 <= 256u) {
                // warp 0 sorts alone: no block barriers in the phase loop
                if (tid < 32u) {
                    for (unsigned k2 = 2; k2 <= np2; k2 <<= 1) {
                        for (unsigned j2 = k2 >> 1; j2 > 0; j2 >>= 1) {
                            for (unsigned t = tid; t < np2 / 2; t += 32u) {
                                unsigned i2 = ((t & ~(j2 - 1)) << 1) | (t & (j2 - 1));
                                unsigned p2 = i2 | j2;
                                unsigned long long a = eqb[i2], b = eqb[p2];
                                bool up = ((i2 & k2) == 0);
                                if ((a < b) == up) { eqb[i2] = b; eqb[p2] = a; }
                            }
                            __syncwarp();
                        }
                    }
                }
                __syncthreads();
            } else {
                for (unsigned k2 = 2; k2 <= np2; k2 <<= 1) { // block bitonic DESC
                    for (unsigned j2 = k2 >> 1; j2 > 0; j2 >>= 1) {
                        for (unsigned t = tid; t < np2 / 2; t += FT) {
                            unsigned i2 = ((t & ~(j2 - 1)) << 1) | (t & (j2 - 1));
                            unsigned p2 = i2 | j2;
                            unsigned long long a = eqb[i2], b = eqb[p2];
                            bool up = ((i2 & k2) == 0);
                            if ((a < b) == up) { eqb[i2] = b; eqb[p2] = a; }
                        }
                        __syncthreads();
                    }
                }
            }
            unsigned long long e = eqb[need2 - 1];       // exact boundary entry
            uT = (unsigned)(e >> 32);
            cut = ~(unsigned)e;                          // largest kept tie idx
            __syncthreads();
        }
    }

    if (need_fb) {
        // ===== exact full-input fallback (cold; never on sane inputs) ========
        unsigned* bins = bcnt;
        unsigned prefix = 0, prefmask = 0, need = KSEL;
        const int vsh[3] = { 21, 10, 0 };
        const int vwd[3] = { 11, 11, 10 };
        for (int r = 0; r < 3; r++) {
            const int sh = vsh[r];
            const int nb = 1 << vwd[r];
            for (int t = tid; t < nb; t += FT) bins[t] = 0;
            __syncthreads();
            for (int i = tid; i < n; i += FT) {
                unsigned u = f2u(x[i]);
                if ((u & prefmask) == prefix) {
                    unsigned b = (u >> sh) & (unsigned)(nb - 1);
                    unsigned am = __activemask();
                    unsigned peers = __match_any_sync(am, b);
                    if ((tid & 31u) == (unsigned)(__ffs(peers) - 1))
                        atomicAdd(&bins[b], (unsigned)__popc(peers));
                }
            }
            __syncthreads();
            for (int d2 = 1; d2 < nb; d2 <<= 1) {      // suffix Hillis-Steele
                unsigned t0 = tid, t1 = tid + FT;
                unsigned a0 = (t0 < (unsigned)nb && t0 + d2 < (unsigned)nb) ? bins[t0 + d2] : 0;
                unsigned a1 = (t1 < (unsigned)nb && t1 + d2 < (unsigned)nb) ? bins[t1 + d2] : 0;
                __syncthreads();
                if (t0 < (unsigned)nb) bins[t0] += a0;
                if (t1 < (unsigned)nb) bins[t1] += a1;
                __syncthreads();
            }
            for (int t = tid; t < nb; t += FT) {
                unsigned nxt = (t + 1 < nb) ? bins[t + 1] : 0;
                if (bins[t] >= need && nxt < need) sh_d = (unsigned)t;
            }
            __syncthreads();
            unsigned d2 = sh_d;
            unsigned above = (d2 + 1 < (unsigned)nb) ? bins[d2 + 1] : 0;
            __syncthreads();
            need -= above;
            prefix |= d2 << sh;
            prefmask |= ((unsigned)(nb - 1)) << sh;
        }
        const unsigned uTf = prefix;
        const unsigned Rf = need;

        unsigned iprefix = 0, imask = 0, needi = Rf;
        const int ish[3] = { 15, 4, 0 };
        const int iwd[3] = { 11, 11, 4 };
        if (Rf > 0) {
            for (int r = 0; r < 3; r++) {
                const int sh = ish[r];
                const int nb = 1 << iwd[r];
                for (int t = tid; t < nb; t += FT) bins[t] = 0;
                __syncthreads();
                for (int i = tid; i < n; i += FT) {
                    unsigned u = f2u(x[i]);
                    if (u == uTf && (((unsigned)i & imask) == iprefix))
                        atomicAdd(&bins[((unsigned)i >> sh) & (unsigned)(nb - 1)], 1u);
                }
                __syncthreads();
                for (int d2 = 1; d2 < nb; d2 <<= 1) {  // prefix Hillis-Steele
                    unsigned t0 = tid, t1 = tid + FT;
                    unsigned a0 = (t0 < (unsigned)nb && t0 >= (unsigned)d2) ? bins[t0 - d2] : 0;
                    unsigned a1 = (t1 < (unsigned)nb && t1 >= (unsigned)d2) ? bins[t1 - d2] : 0;
                    __syncthreads();
                    if (t0 < (unsigned)nb) bins[t0] += a0;
                    if (t1 < (unsigned)nb) bins[t1] += a1;
                    __syncthreads();
                }
                for (int t = tid; t < nb; t += FT) {
                    unsigned prev = (t > 0) ? bins[t - 1] : 0;
                    if (bins[t] >= needi && prev < needi) sh_d = (unsigned)t;
                }
                __syncthreads();
                unsigned d2 = sh_d;
                unsigned below = (d2 > 0) ? bins[d2 - 1] : 0;
                __syncthreads();
                needi -= below;
                iprefix |= d2 << sh;
                imask |= ((unsigned)(nb - 1)) << sh;
            }
        }
        if (tid == 0) g_total = 0;
        __syncthreads();
        for (int i = tid; i < n; i += FT) {
            unsigned u = f2u(x[i]);
            bool keep = (u > uTf) || (Rf > 0 && u == uTf && (unsigned)i <= iprefix);
            if (keep) {
                unsigned p = atomicAdd(&g_total, 1u);
                if (p < CAP) { g_du[p] = u; g_didx[p] = (unsigned)i; }
            }
        }
        __syncthreads();
        T = g_total; if (T > (unsigned)SMEMCAP) T = SMEMCAP;   // == KSEL
        #pragma unroll
        for (int k = 0; k < NPT_CAND; k++) {
            unsigned j = tid + (unsigned)k * FT;
            bool vld = (j < T);
            uk[k] = vld ? g_du[j] : 0u;
            ui[k] = vld ? g_didx[j] : 0u;
        }
        uT = 0; cut = 0xffffffffu;       // every staged candidate is a winner
        // re-zero buckets (fallback dirtied them)
        for (unsigned t = tid; t < NB; t += FT) bcnt[t] = 0;
        __syncthreads();
    }

    // ---- bucket sort by original index: bucket = idx >> 13 (bcnt pre-zeroed)
    #pragma unroll
    for (int k = 0; k < NPT_CAND; k++) {
        unsigned u = uk[k];
        bool keep = (u > uT) || (u == uT && u != 0u && ui[k] <= cut);
        if (keep) atomicAdd(&bcnt[ui[k] >> 13], 1u);
    }
    __syncthreads();

    excl_scan_nb(bcnt, wsum);

    #pragma unroll
    for (int k = 0; k < NPT_CAND; k++) {
        unsigned u = uk[k];
        bool keep = (u > uT) || (u == uT && u != 0u && ui[k] <= cut);
        if (keep) {
            unsigned r = atomicAdd(&bcnt[ui[k] >> 13], 1u);
            if (r < (unsigned)DST_N)
                dst[r] = ((unsigned long long)ui[k] << 32) | (unsigned long long)u;
        }
    }
    __syncthreads();

    // tiny per-bucket insertion sorts (bucket sizes ~0-6)
    for (unsigned b = tid; b < NB; b += FT) {
        unsigned s0 = (b > 0) ? bcnt[b - 1] : 0;
        unsigned e0 = bcnt[b];
        if (s0 > (unsigned)DST_N) s0 = DST_N;
        if (e0 > (unsigned)DST_N) e0 = DST_N;
        for (unsigned i2 = s0 + 1; i2 < e0; i2++) {
            unsigned long long key = dst[i2];
            unsigned j2 = i2;
            while (j2 > s0 && dst[j2 - 1] > key) { dst[j2] = dst[j2 - 1]; j2--; }
            dst[j2] = key;
        }
    }
    __syncthreads();

    for (unsigned t = tid; t < KSEL; t += FT)
        out[t] = u2f((unsigned)(dst[t] & 0xffffffffu));

    // restore invariants for next graph replay
    for (unsigned t = tid; t < NHIST; t += FT) g_hist[t] = 0;
    if (tid == 0) { g_total = 0; g_ovf = 0; }
}

// ---------------- launch ----------------------------------------------------
extern "C" void kernel_launch(void* const* d_in, const int* in_sizes, int n_in,
                              void* d_out, int out_size) {
    const float* x = (const float*)d_in[0];
    int n = in_sizes[0];
    float* out = (float*)d_out;

    cudaFuncSetAttribute(k_final, cudaFuncAttributeMaxDynamicSharedMemorySize, FIN_SMEM);

    k_compact<<<592, 512>>>(x, n);             // 148 SMs x 4 blocks: one wave

    cudaLaunchConfig_t cfg = {};
    cfg.gridDim = dim3(1, 1, 1);
    cfg.blockDim = dim3(FT, 1, 1);
    cfg.dynamicSmemBytes = FIN_SMEM;
    cudaLaunchAttribute attrs[1];
    attrs[0].id = cudaLaunchAttributeProgrammaticStreamSerialization;
    attrs[0].val.programmaticStreamSerializationAllowed = 1;
    cfg.attrs = attrs;
    cfg.numAttrs = 1;
    cudaLaunchKernelEx(&cfg, k_final, x, n, out);
}